// round 8
// baseline (speedup 1.0000x reference)
#include <cuda_runtime.h>
#include <mma.h>
#include <cstdint>

using namespace nvcuda;

#define D_MODEL   2048
#define FFN_DIM   8192
#define HALF_FFN  4096
#define NE        8
#define T_TOKENS  8192
#define MAXROWS   (T_TOKENS * 2)

#define BM 128
#define BK 32
#define LDSF 36                        // 32 + 4 pad floats per smem row
#define DEPTH 3
#define STAGE_B (256 * LDSF * 4)       // A(128 rows) + B(128 rows) = 36864 B
#define DYN_SMEM (DEPTH * STAGE_B)     // 110592 B (epilogue C reuses this)

// ---------------- scratch (device globals; no runtime allocation) ----------
__device__ float g_A[(size_t)MAXROWS * HALF_FFN];       // 256 MB activated up outputs
__device__ float g_Y[(size_t)2 * T_TOKENS * D_MODEL];   // 128 MB per-slot down outputs
__device__ float g_x [(size_t)T_TOKENS * D_MODEL];      // 64 MB tf32-rounded x
__device__ float g_wu[(size_t)NE * FFN_DIM * D_MODEL];  // 512 MB tf32-rounded w_up
__device__ float g_wd[(size_t)NE * D_MODEL * HALF_FFN]; // 256 MB tf32-rounded w_down
__device__ int   g_topk_idx[T_TOKENS][2];
__device__ float g_topk_w[T_TOKENS][2];
__device__ int   g_count[NE];
__device__ int   g_offs[NE + 1];
__device__ int   g_tile_offs[NE + 1];
__device__ int   g_list_token[MAXROWS];
__device__ int   g_list_slot[MAXROWS];
__device__ float g_list_coef[MAXROWS];

// ---------------- PTX helpers ------------------------------------------------
__device__ __forceinline__ uint32_t su32(const void* p) {
    uint32_t r;
    asm("{ .reg .u64 t; cvta.to.shared.u64 t, %1; cvt.u32.u64 %0, t; }"
        : "=r"(r) : "l"(p));
    return r;
}
__device__ __forceinline__ void cp16(uint32_t d, const void* s) {
    asm volatile("cp.async.cg.shared.global [%0], [%1], 16;\n"
                 :: "r"(d), "l"(s) : "memory");
}
__device__ __forceinline__ void cpcommit() {
    asm volatile("cp.async.commit_group;\n" ::: "memory");
}
__device__ __forceinline__ void cpwait2() {
    asm volatile("cp.async.wait_group 2;\n" ::: "memory");
}
__device__ __forceinline__ float tf32rn(float v) {
    float r;
    asm("cvt.rna.tf32.f32 %0, %1;" : "=f"(r) : "f"(v));
    return r;
}

// ---------------- TF32 wmma types (inputs pre-rounded; no per-load cvt) ------
using FragA = wmma::fragment<wmma::matrix_a, 16, 16, 8, wmma::precision::tf32, wmma::row_major>;
using FragB = wmma::fragment<wmma::matrix_b, 16, 16, 8, wmma::precision::tf32, wmma::col_major>;
using FragC = wmma::fragment<wmma::accumulator, 16, 16, 8, float>;

__device__ __forceinline__ int find_expert(int ytile) {
    int e = 0;
#pragma unroll
    for (int i = 0; i < NE; i++) if (ytile >= g_tile_offs[i + 1]) e = i + 1;
    return e;
}

__device__ __forceinline__ float silu_mul(float g, float u) {
    return g * (1.f / (1.f + __expf(-g))) * u;
}

// ---------------- pre-round inputs to tf32 (RNA), once per launch ------------
__global__ void round_kernel(const float4* __restrict__ s, float4* __restrict__ d,
                             int n4) {
    int i = blockIdx.x * blockDim.x + threadIdx.x;
    int stride = gridDim.x * blockDim.x;
    for (; i < n4; i += stride) {
        float4 v = s[i];
        v.x = tf32rn(v.x); v.y = tf32rn(v.y);
        v.z = tf32rn(v.z); v.w = tf32rn(v.w);
        d[i] = v;
    }
}

// ---------------- routing ----------------------------------------------------
__global__ void reset_kernel() {
    if (threadIdx.x < NE) g_count[threadIdx.x] = 0;
}

__global__ void routing_kernel(const float* __restrict__ x,
                               const float* __restrict__ gate_w) {
    int gwarp = (blockIdx.x * blockDim.x + threadIdx.x) >> 5;
    int lane  = threadIdx.x & 31;
    if (gwarp >= T_TOKENS) return;

    const float* xr = x + (size_t)gwarp * D_MODEL;
    float acc[NE];
#pragma unroll
    for (int e = 0; e < NE; e++) acc[e] = 0.f;
    for (int k = lane; k < D_MODEL; k += 32) {
        float xv = xr[k];
#pragma unroll
        for (int e = 0; e < NE; e++) acc[e] += xv * gate_w[e * D_MODEL + k];
    }
#pragma unroll
    for (int off = 16; off > 0; off >>= 1)
#pragma unroll
        for (int e = 0; e < NE; e++)
            acc[e] += __shfl_xor_sync(0xffffffffu, acc[e], off);

    if (lane == 0) {
        int i0 = 0; float b0 = acc[0];
#pragma unroll
        for (int i = 1; i < NE; i++) if (acc[i] > b0) { b0 = acc[i]; i0 = i; }
        int i1 = -1; float b1 = -3.0e38f;
#pragma unroll
        for (int i = 0; i < NE; i++)
            if (i != i0 && acc[i] > b1) { b1 = acc[i]; i1 = i; }
        float e1  = expf(b1 - b0);
        float inv = 1.f / (1.f + e1);
        g_topk_idx[gwarp][0] = i0;  g_topk_idx[gwarp][1] = i1;
        g_topk_w[gwarp][0]   = inv; g_topk_w[gwarp][1]   = e1 * inv;
        atomicAdd(&g_count[i0], 1);
        atomicAdd(&g_count[i1], 1);
    }
}

__global__ void offs_kernel() {
    if (threadIdx.x == 0 && blockIdx.x == 0) {
        int off = 0, toff = 0;
        for (int e = 0; e < NE; e++) {
            g_offs[e] = off; g_tile_offs[e] = toff;
            off  += g_count[e];
            toff += (g_count[e] + BM - 1) >> 7;
        }
        g_offs[NE] = off; g_tile_offs[NE] = toff;
    }
}

__global__ void compact_kernel() {
    int e   = blockIdx.x;
    int tid = threadIdx.x;
    __shared__ int s[1024];
    int base = g_offs[e];
    int run  = 0;
    for (int c0 = 0; c0 < T_TOKENS; c0 += 1024) {
        int t = c0 + tid;
        int sel = 0, slot = 0; float w = 0.f;
        if (t < T_TOKENS) {
            int i0 = g_topk_idx[t][0], i1 = g_topk_idx[t][1];
            if (i0 == e)      { sel = 1; slot = 0; w = g_topk_w[t][0]; }
            else if (i1 == e) { sel = 1; slot = 1; w = g_topk_w[t][1]; }
        }
        s[tid] = sel; __syncthreads();
        for (int d = 1; d < 1024; d <<= 1) {
            int v = (tid >= d) ? s[tid - d] : 0;
            __syncthreads();
            s[tid] += v;
            __syncthreads();
        }
        int incl  = s[tid];
        int total = s[1023];
        if (sel) {
            int r = base + run + incl - 1;
            g_list_token[r] = t;
            g_list_slot[r]  = slot;
            g_list_coef[r]  = w;
        }
        run += total;
        __syncthreads();
    }
}

// ---------------- UP GEMM (fused): g_A = silu(X Wg^T) * (X Wu^T) -------------
// grid (64 n-tiles of 64 over HALF_FFN, 136 m-tiles), band-swizzled (8 m-tiles).
// B stage: rows 0..63 = Wg rows, rows 64..127 = Wu rows.
__global__ void __launch_bounds__(256, 1)
up_gemm() {
    const int tiles_n = 64;
    int b    = blockIdx.y * tiles_n + blockIdx.x;
    int band = b / (8 * tiles_n);
    int rem  = b % (8 * tiles_n);
    int mt   = band * 8 + (rem & 7);
    int nt   = rem >> 3;
    if (mt >= g_tile_offs[NE]) return;

    int e  = find_expert(mt);
    int m0 = (mt - g_tile_offs[e]) * BM;
    int rows = g_count[e] - m0; if (rows > BM) rows = BM;
    int base = g_offs[e];
    int n0   = nt * 64;
    int tid  = threadIdx.x, wid = tid >> 5;

    __shared__ int s_tok[BM];
    extern __shared__ __align__(16) float dynf[];
    uint32_t dbase = su32(dynf);

    if (tid < BM) {
        int rr = (tid < rows) ? tid : (rows - 1);
        s_tok[tid] = g_list_token[base + m0 + rr];
    }
    __syncthreads();

    const float* we = g_wu + (size_t)e * FFN_DIM * D_MODEL;
    int r0 = tid >> 3, q = tid & 7;
    const char* ap[4];
    const char* bp[4];
    uint32_t da[4], dbw[4];
#pragma unroll
    for (int p = 0; p < 4; p++) {
        int r = r0 + 32 * p;
        ap[p] = (const char*)(g_x + (size_t)s_tok[r] * D_MODEL) + q * 16;
        int brow = (p < 2) ? (n0 + r) : (HALF_FFN + n0 + (r - 64));
        bp[p] = (const char*)(we + (size_t)brow * D_MODEL) + q * 16;
        da[p]  = (uint32_t)(r * (LDSF * 4) + q * 16);
        dbw[p] = (uint32_t)(BM * (LDSF * 4) + r * (LDSF * 4) + q * 16);
    }

    int wm = (wid & 3) * 32;          // 4 m-strips of 32
    int wn = (wid >> 2) * 32;         // 2 n-strips of 32

    FragC accg[2][2], accu[2][2];
#pragma unroll
    for (int i = 0; i < 2; i++)
#pragma unroll
        for (int j = 0; j < 2; j++) {
            wmma::fill_fragment(accg[i][j], 0.f);
            wmma::fill_fragment(accu[i][j], 0.f);
        }

    const int KT = D_MODEL / BK;      // 64

#define UP_ISSUE(J) do {                                                     \
    uint32_t sb = dbase + ((J) % DEPTH) * STAGE_B;                           \
    size_t ko = (size_t)(J) * 128;                                           \
    _Pragma("unroll")                                                        \
    for (int p = 0; p < 4; p++) {                                            \
        cp16(sb + da[p],  ap[p] + ko);                                       \
        cp16(sb + dbw[p], bp[p] + ko);                                       \
    }                                                                        \
    cpcommit();                                                              \
} while (0)

    UP_ISSUE(0);
    UP_ISSUE(1);

#pragma unroll 1
    for (int kt = 0; kt < KT; kt++) {
        int jn = kt + DEPTH - 1;
        if (jn < KT) { UP_ISSUE(jn); } else { cpcommit(); }
        cpwait2();
        __syncthreads();

        float* As = dynf + (kt % DEPTH) * (STAGE_B / 4);
        float* Bs = As + BM * LDSF;
#pragma unroll
        for (int ks = 0; ks < BK / 8; ks++) {
            FragA af[2]; FragB bg[2], bu[2];
#pragma unroll
            for (int i = 0; i < 2; i++)
                wmma::load_matrix_sync(af[i], As + (wm + i * 16) * LDSF + ks * 8, LDSF);
#pragma unroll
            for (int j = 0; j < 2; j++) {
                wmma::load_matrix_sync(bg[j], Bs + (wn + j * 16) * LDSF + ks * 8, LDSF);
                wmma::load_matrix_sync(bu[j], Bs + (64 + wn + j * 16) * LDSF + ks * 8, LDSF);
            }
#pragma unroll
            for (int i = 0; i < 2; i++)
#pragma unroll
                for (int j = 0; j < 2; j++) {
                    wmma::mma_sync(accg[i][j], af[i], bg[j], accg[i][j]);
                    wmma::mma_sync(accu[i][j], af[i], bu[j], accu[i][j]);
                }
        }
        __syncthreads();
    }
#undef UP_ISSUE

    // epilogue: silu(Cg)*Cu (tf32-rounded) -> g_A   (Cg, Cu staged in smem)
    float* Cg = dynf;
    float* Cu = dynf + 128 * 64;
#pragma unroll
    for (int i = 0; i < 2; i++)
#pragma unroll
        for (int j = 0; j < 2; j++) {
            wmma::store_matrix_sync(Cg + (wm + i * 16) * 64 + wn + j * 16,
                                    accg[i][j], 64, wmma::mem_row_major);
            wmma::store_matrix_sync(Cu + (wm + i * 16) * 64 + wn + j * 16,
                                    accu[i][j], 64, wmma::mem_row_major);
        }
    __syncthreads();

#pragma unroll
    for (int it = 0; it < 8; it++) {
        int idx = tid + it * 256;
        int row = idx >> 4;
        int col = (idx & 15) * 4;
        if (row < rows) {
            float4 g = *(const float4*)(Cg + row * 64 + col);
            float4 u = *(const float4*)(Cu + row * 64 + col);
            float4 v;
            v.x = tf32rn(silu_mul(g.x, u.x));
            v.y = tf32rn(silu_mul(g.y, u.y));
            v.z = tf32rn(silu_mul(g.z, u.z));
            v.w = tf32rn(silu_mul(g.w, u.w));
            *(float4*)(g_A + (size_t)(base + m0 + row) * HALF_FFN + n0 + col) = v;
        }
    }
}

// ---------------- DOWN GEMM: g_Y[slot] = coef * (g_A Wdown^T) ----------------
// grid (16 n-tiles of 128 over D_MODEL, 136 m-tiles), same band swizzle.
__global__ void __launch_bounds__(256, 1)
down_gemm() {
    const int tiles_n = 16;
    int b    = blockIdx.y * tiles_n + blockIdx.x;
    int band = b / (8 * tiles_n);
    int rem  = b % (8 * tiles_n);
    int mt   = band * 8 + (rem & 7);
    int nt   = rem >> 3;
    if (mt >= g_tile_offs[NE]) return;

    int e  = find_expert(mt);
    int m0 = (mt - g_tile_offs[e]) * BM;
    int rows = g_count[e] - m0; if (rows > BM) rows = BM;
    int base = g_offs[e];
    int n0   = nt * 128;
    int tid  = threadIdx.x, wid = tid >> 5;

    __shared__ int   s_tk[BM];
    __shared__ int   s_sl[BM];
    __shared__ float s_cf[BM];
    extern __shared__ __align__(16) float dynf[];
    uint32_t dbase = su32(dynf);

    if (tid < BM) {
        if (tid < rows) {
            s_tk[tid] = g_list_token[base + m0 + tid];
            s_sl[tid] = g_list_slot[base + m0 + tid];
            s_cf[tid] = g_list_coef[base + m0 + tid];
        } else { s_tk[tid] = 0; s_sl[tid] = 0; s_cf[tid] = 0.f; }
    }
    __syncthreads();

    const float* we = g_wd + (size_t)e * D_MODEL * HALF_FFN;
    int r0 = tid >> 3, q = tid & 7;
    const char* ap[4];
    const char* bp[4];
    uint32_t da[4], dbw[4];
#pragma unroll
    for (int p = 0; p < 4; p++) {
        int r = r0 + 32 * p;
        int ar = (r < rows) ? r : (rows - 1);
        ap[p] = (const char*)(g_A + (size_t)(base + m0 + ar) * HALF_FFN) + q * 16;
        bp[p] = (const char*)(we + (size_t)(n0 + r) * HALF_FFN) + q * 16;
        da[p]  = (uint32_t)(r * (LDSF * 4) + q * 16);
        dbw[p] = (uint32_t)(BM * (LDSF * 4) + r * (LDSF * 4) + q * 16);
    }

    int wm = (wid & 3) * 32;          // 4 m-strips of 32
    int wn = (wid >> 2) * 64;         // 2 n-strips of 64

    FragC acc[2][4];
#pragma unroll
    for (int i = 0; i < 2; i++)
#pragma unroll
        for (int j = 0; j < 4; j++) wmma::fill_fragment(acc[i][j], 0.f);

    const int KT = HALF_FFN / BK;     // 128

#define DN_ISSUE(J) do {                                                     \
    uint32_t sb = dbase + ((J) % DEPTH) * STAGE_B;                           \
    size_t ko = (size_t)(J) * 128;                                           \
    _Pragma("unroll")                                                        \
    for (int p = 0; p < 4; p++) {                                            \
        cp16(sb + da[p],  ap[p] + ko);                                       \
        cp16(sb + dbw[p], bp[p] + ko);                                       \
    }                                                                        \
    cpcommit();                                                              \
} while (0)

    DN_ISSUE(0);
    DN_ISSUE(1);

#pragma unroll 1
    for (int kt = 0; kt < KT; kt++) {
        int jn = kt + DEPTH - 1;
        if (jn < KT) { DN_ISSUE(jn); } else { cpcommit(); }
        cpwait2();
        __syncthreads();

        float* As = dynf + (kt % DEPTH) * (STAGE_B / 4);
        float* Bs = As + BM * LDSF;
#pragma unroll
        for (int ks = 0; ks < BK / 8; ks++) {
            FragA af[2]; FragB bf[4];
#pragma unroll
            for (int i = 0; i < 2; i++)
                wmma::load_matrix_sync(af[i], As + (wm + i * 16) * LDSF + ks * 8, LDSF);
#pragma unroll
            for (int j = 0; j < 4; j++)
                wmma::load_matrix_sync(bf[j], Bs + (wn + j * 16) * LDSF + ks * 8, LDSF);
#pragma unroll
            for (int i = 0; i < 2; i++)
#pragma unroll
                for (int j = 0; j < 4; j++)
                    wmma::mma_sync(acc[i][j], af[i], bf[j], acc[i][j]);
        }
        __syncthreads();
    }
#undef DN_ISSUE

    // epilogue: scale by coef, scatter to g_Y (C staged in smem, 64 KB)
    float* Cs = dynf;
#pragma unroll
    for (int i = 0; i < 2; i++)
#pragma unroll
        for (int j = 0; j < 4; j++)
            wmma::store_matrix_sync(Cs + (wm + i * 16) * 128 + wn + j * 16,
                                    acc[i][j], 128, wmma::mem_row_major);
    __syncthreads();

#pragma unroll
    for (int it = 0; it < 16; it++) {
        int idx = tid + it * 256;
        int row = idx >> 5;
        int col = (idx & 31) * 4;
        if (row < rows) {
            float c = s_cf[row];
            float4 v = *(const float4*)(Cs + row * 128 + col);
            v.x *= c; v.y *= c; v.z *= c; v.w *= c;
            *(float4*)(g_Y + ((size_t)s_sl[row] * T_TOKENS + s_tk[row]) * D_MODEL
                           + n0 + col) = v;
        }
    }
}

__global__ void combine_kernel(float* __restrict__ out) {
    size_t i = (size_t)blockIdx.x * blockDim.x + threadIdx.x;
    const size_t n4 = (size_t)T_TOKENS * D_MODEL / 4;
    if (i < n4) {
        const float4* y = (const float4*)g_Y;
        float4 a = y[i], b = y[i + n4];
        float4 r;
        r.x = a.x + b.x; r.y = a.y + b.y; r.z = a.z + b.z; r.w = a.w + b.w;
        ((float4*)out)[i] = r;
    }
}

// ---------------- host entry -------------------------------------------------
extern "C" void kernel_launch(void* const* d_in, const int* in_sizes, int n_in,
                              void* d_out, int out_size) {
    const float* x      = (const float*)d_in[0];
    const float* gate_w = (const float*)d_in[1];
    const float* w_up   = (const float*)d_in[2];
    const float* w_down = (const float*)d_in[3];
    float* out = (float*)d_out;

    cudaFuncSetAttribute(up_gemm,   cudaFuncAttributeMaxDynamicSharedMemorySize, DYN_SMEM);
    cudaFuncSetAttribute(down_gemm, cudaFuncAttributeMaxDynamicSharedMemorySize, DYN_SMEM);

    float* d_gx; cudaGetSymbolAddress((void**)&d_gx, g_x);
    float* d_wu; cudaGetSymbolAddress((void**)&d_wu, g_wu);
    float* d_wd; cudaGetSymbolAddress((void**)&d_wd, g_wd);

    reset_kernel<<<1, 32>>>();
    routing_kernel<<<T_TOKENS / 8, 256>>>(x, gate_w);   // routing uses raw x
    offs_kernel<<<1, 1>>>();
    compact_kernel<<<NE, 1024>>>();

    // one-time tf32 RNA pre-rounding (removes all per-load cvt in the GEMMs)
    round_kernel<<<1184, 256>>>((const float4*)x,      (float4*)d_gx,
                                T_TOKENS * D_MODEL / 4);
    round_kernel<<<1184, 256>>>((const float4*)w_up,   (float4*)d_wu,
                                NE * FFN_DIM * D_MODEL / 4);
    round_kernel<<<1184, 256>>>((const float4*)w_down, (float4*)d_wd,
                                NE * D_MODEL * HALF_FFN / 4);

    up_gemm<<<dim3(64, 136, 1), 256, DYN_SMEM>>>();
    down_gemm<<<dim3(16, 136, 1), 256, DYN_SMEM>>>();

    combine_kernel<<<(T_TOKENS * D_MODEL / 4 + 255) / 256, 256>>>(out);
}

// round 9
// speedup vs baseline: 1.3730x; 1.3730x over previous
#include <cuda_runtime.h>
#include <mma.h>
#include <cstdint>

using namespace nvcuda;

#define D_MODEL   2048
#define FFN_DIM   8192
#define HALF_FFN  4096
#define NE        8
#define T_TOKENS  8192
#define MAXROWS   (T_TOKENS * 2)

#define BM 128
#define BK 32
#define LDSF 36                        // 32 + 4 pad floats per smem row
#define DEPTH 3
#define STAGE_B (256 * LDSF * 4)       // A(128 rows) + B(128 rows) = 36864 B
#define DYN_SMEM (DEPTH * STAGE_B)     // 110592 B; 2 CTAs/SM = 221184 <= 233472

// ---------------- scratch (device globals; no runtime allocation) ----------
__device__ float g_A[(size_t)MAXROWS * HALF_FFN];       // 256 MB activated up outputs
__device__ float g_Y[(size_t)2 * T_TOKENS * D_MODEL];   // 128 MB per-slot down outputs
__device__ int   g_topk_idx[T_TOKENS][2];
__device__ float g_topk_w[T_TOKENS][2];
__device__ int   g_count[NE];
__device__ int   g_offs[NE + 1];
__device__ int   g_tile_offs[NE + 1];
__device__ int   g_list_token[MAXROWS];
__device__ int   g_list_slot[MAXROWS];
__device__ float g_list_coef[MAXROWS];

// ---------------- PTX helpers ------------------------------------------------
__device__ __forceinline__ uint32_t su32(const void* p) {
    uint32_t r;
    asm("{ .reg .u64 t; cvta.to.shared.u64 t, %1; cvt.u32.u64 %0, t; }"
        : "=r"(r) : "l"(p));
    return r;
}
__device__ __forceinline__ void cp16(uint32_t d, const void* s) {
    asm volatile("cp.async.cg.shared.global [%0], [%1], 16;\n"
                 :: "r"(d), "l"(s) : "memory");
}
__device__ __forceinline__ void cpcommit() {
    asm volatile("cp.async.commit_group;\n" ::: "memory");
}
__device__ __forceinline__ void cpwait2() {
    asm volatile("cp.async.wait_group 2;\n" ::: "memory");
}

// ---------------- TF32 wmma types -------------------------------------------
using FragA = wmma::fragment<wmma::matrix_a, 16, 16, 8, wmma::precision::tf32, wmma::row_major>;
using FragB = wmma::fragment<wmma::matrix_b, 16, 16, 8, wmma::precision::tf32, wmma::col_major>;
using FragC = wmma::fragment<wmma::accumulator, 16, 16, 8, float>;

template <typename Frag>
__device__ __forceinline__ void to_tf32(Frag& f) {
#pragma unroll
    for (int i = 0; i < f.num_elements; i++) f.x[i] = wmma::__float_to_tf32(f.x[i]);
}

__device__ __forceinline__ int find_expert(int ytile) {
    int e = 0;
#pragma unroll
    for (int i = 0; i < NE; i++) if (ytile >= g_tile_offs[i + 1]) e = i + 1;
    return e;
}

__device__ __forceinline__ float silu_mul(float g, float u) {
    return g * (1.f / (1.f + __expf(-g))) * u;
}

// ---------------- routing ----------------------------------------------------
__global__ void reset_kernel() {
    if (threadIdx.x < NE) g_count[threadIdx.x] = 0;
}

__global__ void routing_kernel(const float* __restrict__ x,
                               const float* __restrict__ gate_w) {
    int gwarp = (blockIdx.x * blockDim.x + threadIdx.x) >> 5;
    int lane  = threadIdx.x & 31;
    if (gwarp >= T_TOKENS) return;

    const float* xr = x + (size_t)gwarp * D_MODEL;
    float acc[NE];
#pragma unroll
    for (int e = 0; e < NE; e++) acc[e] = 0.f;
    for (int k = lane; k < D_MODEL; k += 32) {
        float xv = xr[k];
#pragma unroll
        for (int e = 0; e < NE; e++) acc[e] += xv * gate_w[e * D_MODEL + k];
    }
#pragma unroll
    for (int off = 16; off > 0; off >>= 1)
#pragma unroll
        for (int e = 0; e < NE; e++)
            acc[e] += __shfl_xor_sync(0xffffffffu, acc[e], off);

    if (lane == 0) {
        int i0 = 0; float b0 = acc[0];
#pragma unroll
        for (int i = 1; i < NE; i++) if (acc[i] > b0) { b0 = acc[i]; i0 = i; }
        int i1 = -1; float b1 = -3.0e38f;
#pragma unroll
        for (int i = 0; i < NE; i++)
            if (i != i0 && acc[i] > b1) { b1 = acc[i]; i1 = i; }
        float e1  = expf(b1 - b0);
        float inv = 1.f / (1.f + e1);
        g_topk_idx[gwarp][0] = i0;  g_topk_idx[gwarp][1] = i1;
        g_topk_w[gwarp][0]   = inv; g_topk_w[gwarp][1]   = e1 * inv;
        atomicAdd(&g_count[i0], 1);
        atomicAdd(&g_count[i1], 1);
    }
}

__global__ void offs_kernel() {
    if (threadIdx.x == 0 && blockIdx.x == 0) {
        int off = 0, toff = 0;
        for (int e = 0; e < NE; e++) {
            g_offs[e] = off; g_tile_offs[e] = toff;
            off  += g_count[e];
            toff += (g_count[e] + BM - 1) >> 7;
        }
        g_offs[NE] = off; g_tile_offs[NE] = toff;
    }
}

__global__ void compact_kernel() {
    int e   = blockIdx.x;
    int tid = threadIdx.x;
    __shared__ int s[1024];
    int base = g_offs[e];
    int run  = 0;
    for (int c0 = 0; c0 < T_TOKENS; c0 += 1024) {
        int t = c0 + tid;
        int sel = 0, slot = 0; float w = 0.f;
        if (t < T_TOKENS) {
            int i0 = g_topk_idx[t][0], i1 = g_topk_idx[t][1];
            if (i0 == e)      { sel = 1; slot = 0; w = g_topk_w[t][0]; }
            else if (i1 == e) { sel = 1; slot = 1; w = g_topk_w[t][1]; }
        }
        s[tid] = sel; __syncthreads();
        for (int d = 1; d < 1024; d <<= 1) {
            int v = (tid >= d) ? s[tid - d] : 0;
            __syncthreads();
            s[tid] += v;
            __syncthreads();
        }
        int incl  = s[tid];
        int total = s[1023];
        if (sel) {
            int r = base + run + incl - 1;
            g_list_token[r] = t;
            g_list_slot[r]  = slot;
            g_list_coef[r]  = w;
        }
        run += total;
        __syncthreads();
    }
}

// ---------------- UP GEMM (fused): g_A = silu(X Wg^T) * (X Wu^T) -------------
// grid (64 n-tiles of 64 over HALF_FFN, 136 m-tiles), band-swizzled (8 m-tiles).
// B stage: rows 0..63 = Wg rows, rows 64..127 = Wu rows. 2 CTAs per SM.
__global__ void __launch_bounds__(256, 2)
up_gemm(const float* __restrict__ x, const float* __restrict__ w_up) {
    const int tiles_n = 64;
    int b    = blockIdx.y * tiles_n + blockIdx.x;
    int band = b / (8 * tiles_n);
    int rem  = b % (8 * tiles_n);
    int mt   = band * 8 + (rem & 7);
    int nt   = rem >> 3;
    if (mt >= g_tile_offs[NE]) return;

    int e  = find_expert(mt);
    int m0 = (mt - g_tile_offs[e]) * BM;
    int rows = g_count[e] - m0; if (rows > BM) rows = BM;
    int base = g_offs[e];
    int n0   = nt * 64;
    int tid  = threadIdx.x, wid = tid >> 5;

    __shared__ int s_tok[BM];
    extern __shared__ __align__(16) float dynf[];
    uint32_t dbase = su32(dynf);

    if (tid < BM) {
        int rr = (tid < rows) ? tid : (rows - 1);
        s_tok[tid] = g_list_token[base + m0 + rr];
    }
    __syncthreads();

    const float* we = w_up + (size_t)e * FFN_DIM * D_MODEL;
    int r0 = tid >> 3, q = tid & 7;
    const char* ap[4];
    const char* bp[4];
    uint32_t da[4], dbw[4];
#pragma unroll
    for (int p = 0; p < 4; p++) {
        int r = r0 + 32 * p;
        ap[p] = (const char*)(x + (size_t)s_tok[r] * D_MODEL) + q * 16;
        int brow = (p < 2) ? (n0 + r) : (HALF_FFN + n0 + (r - 64));
        bp[p] = (const char*)(we + (size_t)brow * D_MODEL) + q * 16;
        da[p]  = (uint32_t)(r * (LDSF * 4) + q * 16);
        dbw[p] = (uint32_t)(BM * (LDSF * 4) + r * (LDSF * 4) + q * 16);
    }

    int wm = (wid & 3) * 32;          // 4 m-strips of 32
    int wn = (wid >> 2) * 32;         // 2 n-strips of 32

    FragC accg[2][2], accu[2][2];
#pragma unroll
    for (int i = 0; i < 2; i++)
#pragma unroll
        for (int j = 0; j < 2; j++) {
            wmma::fill_fragment(accg[i][j], 0.f);
            wmma::fill_fragment(accu[i][j], 0.f);
        }

    const int KT = D_MODEL / BK;      // 64

#define UP_ISSUE(J) do {                                                     \
    uint32_t sb = dbase + ((J) % DEPTH) * STAGE_B;                           \
    size_t ko = (size_t)(J) * 128;                                           \
    _Pragma("unroll")                                                        \
    for (int p = 0; p < 4; p++) {                                            \
        cp16(sb + da[p],  ap[p] + ko);                                       \
        cp16(sb + dbw[p], bp[p] + ko);                                       \
    }                                                                        \
    cpcommit();                                                              \
} while (0)

    UP_ISSUE(0);
    UP_ISSUE(1);

#pragma unroll 1
    for (int kt = 0; kt < KT; kt++) {
        int jn = kt + DEPTH - 1;
        if (jn < KT) { UP_ISSUE(jn); } else { cpcommit(); }
        cpwait2();
        __syncthreads();

        float* As = dynf + (kt % DEPTH) * (STAGE_B / 4);
        float* Bs = As + BM * LDSF;
#pragma unroll
        for (int ks = 0; ks < BK / 8; ks++) {
            FragA af[2]; FragB bg[2], bu[2];
#pragma unroll
            for (int i = 0; i < 2; i++) {
                wmma::load_matrix_sync(af[i], As + (wm + i * 16) * LDSF + ks * 8, LDSF);
                to_tf32(af[i]);
            }
#pragma unroll
            for (int j = 0; j < 2; j++) {
                wmma::load_matrix_sync(bg[j], Bs + (wn + j * 16) * LDSF + ks * 8, LDSF);
                to_tf32(bg[j]);
                wmma::load_matrix_sync(bu[j], Bs + (64 + wn + j * 16) * LDSF + ks * 8, LDSF);
                to_tf32(bu[j]);
            }
#pragma unroll
            for (int i = 0; i < 2; i++)
#pragma unroll
                for (int j = 0; j < 2; j++) {
                    wmma::mma_sync(accg[i][j], af[i], bg[j], accg[i][j]);
                    wmma::mma_sync(accu[i][j], af[i], bu[j], accu[i][j]);
                }
        }
        __syncthreads();
    }
#undef UP_ISSUE

    // epilogue: silu(Cg)*Cu -> g_A   (Cg, Cu staged in smem, 32 KB each)
    float* Cg = dynf;
    float* Cu = dynf + 128 * 64;
#pragma unroll
    for (int i = 0; i < 2; i++)
#pragma unroll
        for (int j = 0; j < 2; j++) {
            wmma::store_matrix_sync(Cg + (wm + i * 16) * 64 + wn + j * 16,
                                    accg[i][j], 64, wmma::mem_row_major);
            wmma::store_matrix_sync(Cu + (wm + i * 16) * 64 + wn + j * 16,
                                    accu[i][j], 64, wmma::mem_row_major);
        }
    __syncthreads();

#pragma unroll
    for (int it = 0; it < 8; it++) {
        int idx = tid + it * 256;
        int row = idx >> 4;
        int col = (idx & 15) * 4;
        if (row < rows) {
            float4 g = *(const float4*)(Cg + row * 64 + col);
            float4 u = *(const float4*)(Cu + row * 64 + col);
            float4 v;
            v.x = silu_mul(g.x, u.x);
            v.y = silu_mul(g.y, u.y);
            v.z = silu_mul(g.z, u.z);
            v.w = silu_mul(g.w, u.w);
            *(float4*)(g_A + (size_t)(base + m0 + row) * HALF_FFN + n0 + col) = v;
        }
    }
}

// ---------------- DOWN GEMM: g_Y[slot] = coef * (g_A Wdown^T) ----------------
// grid (16 n-tiles of 128 over D_MODEL, 136 m-tiles), same band swizzle.
__global__ void __launch_bounds__(256, 2)
down_gemm(const float* __restrict__ w_down) {
    const int tiles_n = 16;
    int b    = blockIdx.y * tiles_n + blockIdx.x;
    int band = b / (8 * tiles_n);
    int rem  = b % (8 * tiles_n);
    int mt   = band * 8 + (rem & 7);
    int nt   = rem >> 3;
    if (mt >= g_tile_offs[NE]) return;

    int e  = find_expert(mt);
    int m0 = (mt - g_tile_offs[e]) * BM;
    int rows = g_count[e] - m0; if (rows > BM) rows = BM;
    int base = g_offs[e];
    int n0   = nt * 128;
    int tid  = threadIdx.x, wid = tid >> 5;

    __shared__ int   s_tk[BM];
    __shared__ int   s_sl[BM];
    __shared__ float s_cf[BM];
    extern __shared__ __align__(16) float dynf[];
    uint32_t dbase = su32(dynf);

    if (tid < BM) {
        if (tid < rows) {
            s_tk[tid] = g_list_token[base + m0 + tid];
            s_sl[tid] = g_list_slot[base + m0 + tid];
            s_cf[tid] = g_list_coef[base + m0 + tid];
        } else { s_tk[tid] = 0; s_sl[tid] = 0; s_cf[tid] = 0.f; }
    }
    __syncthreads();

    const float* we = w_down + (size_t)e * D_MODEL * HALF_FFN;
    int r0 = tid >> 3, q = tid & 7;
    const char* ap[4];
    const char* bp[4];
    uint32_t da[4], dbw[4];
#pragma unroll
    for (int p = 0; p < 4; p++) {
        int r = r0 + 32 * p;
        int ar = (r < rows) ? r : (rows - 1);
        ap[p] = (const char*)(g_A + (size_t)(base + m0 + ar) * HALF_FFN) + q * 16;
        bp[p] = (const char*)(we + (size_t)(n0 + r) * HALF_FFN) + q * 16;
        da[p]  = (uint32_t)(r * (LDSF * 4) + q * 16);
        dbw[p] = (uint32_t)(BM * (LDSF * 4) + r * (LDSF * 4) + q * 16);
    }

    int wm = (wid & 3) * 32;          // 4 m-strips of 32
    int wn = (wid >> 2) * 64;         // 2 n-strips of 64

    FragC acc[2][4];
#pragma unroll
    for (int i = 0; i < 2; i++)
#pragma unroll
        for (int j = 0; j < 4; j++) wmma::fill_fragment(acc[i][j], 0.f);

    const int KT = HALF_FFN / BK;     // 128

#define DN_ISSUE(J) do {                                                     \
    uint32_t sb = dbase + ((J) % DEPTH) * STAGE_B;                           \
    size_t ko = (size_t)(J) * 128;                                           \
    _Pragma("unroll")                                                        \
    for (int p = 0; p < 4; p++) {                                            \
        cp16(sb + da[p],  ap[p] + ko);                                       \
        cp16(sb + dbw[p], bp[p] + ko);                                       \
    }                                                                        \
    cpcommit();                                                              \
} while (0)

    DN_ISSUE(0);
    DN_ISSUE(1);

#pragma unroll 1
    for (int kt = 0; kt < KT; kt++) {
        int jn = kt + DEPTH - 1;
        if (jn < KT) { DN_ISSUE(jn); } else { cpcommit(); }
        cpwait2();
        __syncthreads();

        float* As = dynf + (kt % DEPTH) * (STAGE_B / 4);
        float* Bs = As + BM * LDSF;
#pragma unroll
        for (int ks = 0; ks < BK / 8; ks++) {
            FragA af[2]; FragB bf[4];
#pragma unroll
            for (int i = 0; i < 2; i++) {
                wmma::load_matrix_sync(af[i], As + (wm + i * 16) * LDSF + ks * 8, LDSF);
                to_tf32(af[i]);
            }
#pragma unroll
            for (int j = 0; j < 4; j++) {
                wmma::load_matrix_sync(bf[j], Bs + (wn + j * 16) * LDSF + ks * 8, LDSF);
                to_tf32(bf[j]);
            }
#pragma unroll
            for (int i = 0; i < 2; i++)
#pragma unroll
                for (int j = 0; j < 4; j++)
                    wmma::mma_sync(acc[i][j], af[i], bf[j], acc[i][j]);
        }
        __syncthreads();
    }
#undef DN_ISSUE

    // epilogue: scale by coef, scatter to g_Y (C staged in smem, 64 KB)
    float* Cs = dynf;
#pragma unroll
    for (int i = 0; i < 2; i++)
#pragma unroll
        for (int j = 0; j < 4; j++)
            wmma::store_matrix_sync(Cs + (wm + i * 16) * 128 + wn + j * 16,
                                    acc[i][j], 128, wmma::mem_row_major);
    __syncthreads();

#pragma unroll
    for (int it = 0; it < 16; it++) {
        int idx = tid + it * 256;
        int row = idx >> 5;
        int col = (idx & 31) * 4;
        if (row < rows) {
            float c = s_cf[row];
            float4 v = *(const float4*)(Cs + row * 128 + col);
            v.x *= c; v.y *= c; v.z *= c; v.w *= c;
            *(float4*)(g_Y + ((size_t)s_sl[row] * T_TOKENS + s_tk[row]) * D_MODEL
                           + n0 + col) = v;
        }
    }
}

__global__ void combine_kernel(float* __restrict__ out) {
    size_t i = (size_t)blockIdx.x * blockDim.x + threadIdx.x;
    const size_t n4 = (size_t)T_TOKENS * D_MODEL / 4;
    if (i < n4) {
        const float4* y = (const float4*)g_Y;
        float4 a = y[i], b = y[i + n4];
        float4 r;
        r.x = a.x + b.x; r.y = a.y + b.y; r.z = a.z + b.z; r.w = a.w + b.w;
        ((float4*)out)[i] = r;
    }
}

// ---------------- host entry -------------------------------------------------
extern "C" void kernel_launch(void* const* d_in, const int* in_sizes, int n_in,
                              void* d_out, int out_size) {
    const float* x      = (const float*)d_in[0];
    const float* gate_w = (const float*)d_in[1];
    const float* w_up   = (const float*)d_in[2];
    const float* w_down = (const float*)d_in[3];
    float* out = (float*)d_out;

    cudaFuncSetAttribute(up_gemm,   cudaFuncAttributeMaxDynamicSharedMemorySize, DYN_SMEM);
    cudaFuncSetAttribute(down_gemm, cudaFuncAttributeMaxDynamicSharedMemorySize, DYN_SMEM);

    reset_kernel<<<1, 32>>>();
    routing_kernel<<<T_TOKENS / 8, 256>>>(x, gate_w);
    offs_kernel<<<1, 1>>>();
    compact_kernel<<<NE, 1024>>>();

    // up: 64 n-tiles (64 cols of HALF_FFN each, g+u) x 136 m-tiles
    up_gemm<<<dim3(64, 136, 1), 256, DYN_SMEM>>>(x, w_up);
    // down: 16 n-tiles (128 cols of D_MODEL) x 136 m-tiles
    down_gemm<<<dim3(16, 136, 1), 256, DYN_SMEM>>>(w_down);

    combine_kernel<<<(T_TOKENS * D_MODEL / 4 + 255) / 256, 256>>>(out);
}

// round 10
// speedup vs baseline: 5.6256x; 4.0973x over previous
#include <cuda_runtime.h>
#include <cuda_fp16.h>
#include <mma.h>
#include <cstdint>

using namespace nvcuda;

#define D_MODEL   2048
#define FFN_DIM   8192
#define HALF_FFN  4096
#define NE        8
#define T_TOKENS  8192
#define MAXROWS   (T_TOKENS * 2)

#define BM 128
#define BKH 64                         // k elements per tile (fp16) = 128 B/row
#define LDSH 72                        // 64 + 8 pad halfs per smem row (144 B)
#define DEPTH 3
#define STAGE_B (256 * LDSH * 2)       // A(128 rows) + B(128 rows) = 36864 B
#define DYN_SMEM (DEPTH * STAGE_B)     // 110592 B; 2 CTAs/SM

// ---------------- scratch (device globals; no runtime allocation) ----------
__device__ __half g_xh [(size_t)T_TOKENS * D_MODEL];        // 32 MB fp16 x
__device__ __half g_wuh[(size_t)NE * FFN_DIM * D_MODEL];    // 384 MB fp16 w_up
__device__ __half g_wdh[(size_t)NE * D_MODEL * HALF_FFN];   // 192 MB fp16 w_down
__device__ __half g_A  [(size_t)MAXROWS * HALF_FFN];        // 128 MB fp16 activated
__device__ float  g_Y  [(size_t)2 * T_TOKENS * D_MODEL];    // 128 MB per-slot outputs
__device__ int    g_topk_idx[T_TOKENS][2];
__device__ float  g_topk_w[T_TOKENS][2];
__device__ int    g_count[NE];
__device__ int    g_offs[NE + 1];
__device__ int    g_tile_offs[NE + 1];
__device__ int    g_list_token[MAXROWS];
__device__ int    g_list_slot[MAXROWS];
__device__ float  g_list_coef[MAXROWS];

// ---------------- PTX helpers ------------------------------------------------
__device__ __forceinline__ uint32_t su32(const void* p) {
    uint32_t r;
    asm("{ .reg .u64 t; cvta.to.shared.u64 t, %1; cvt.u32.u64 %0, t; }"
        : "=r"(r) : "l"(p));
    return r;
}
__device__ __forceinline__ void cp16(uint32_t d, const void* s) {
    asm volatile("cp.async.cg.shared.global [%0], [%1], 16;\n"
                 :: "r"(d), "l"(s) : "memory");
}
__device__ __forceinline__ void cpcommit() {
    asm volatile("cp.async.commit_group;\n" ::: "memory");
}
__device__ __forceinline__ void cpwait2() {
    asm volatile("cp.async.wait_group 2;\n" ::: "memory");
}

// ---------------- FP16 wmma types (fp32 accumulate) --------------------------
using FragA = wmma::fragment<wmma::matrix_a, 16, 16, 16, __half, wmma::row_major>;
using FragB = wmma::fragment<wmma::matrix_b, 16, 16, 16, __half, wmma::col_major>;
using FragC = wmma::fragment<wmma::accumulator, 16, 16, 16, float>;

__device__ __forceinline__ int find_expert(int ytile) {
    int e = 0;
#pragma unroll
    for (int i = 0; i < NE; i++) if (ytile >= g_tile_offs[i + 1]) e = i + 1;
    return e;
}

__device__ __forceinline__ float silu_mul(float g, float u) {
    return g * (1.f / (1.f + __expf(-g))) * u;
}

// ---------------- fp32 -> fp16 conversion (once per launch) ------------------
__global__ void cvt_kernel(const float4* __restrict__ s, uint2* __restrict__ d,
                           int n4) {
    int i = blockIdx.x * blockDim.x + threadIdx.x;
    int stride = gridDim.x * blockDim.x;
    for (; i < n4; i += stride) {
        float4 v = s[i];
        __half2 a = __floats2half2_rn(v.x, v.y);
        __half2 b = __floats2half2_rn(v.z, v.w);
        uint2 o;
        o.x = *(const uint32_t*)&a;
        o.y = *(const uint32_t*)&b;
        d[i] = o;
    }
}

// ---------------- routing ----------------------------------------------------
__global__ void reset_kernel() {
    if (threadIdx.x < NE) g_count[threadIdx.x] = 0;
}

__global__ void routing_kernel(const float* __restrict__ x,
                               const float* __restrict__ gate_w) {
    int gwarp = (blockIdx.x * blockDim.x + threadIdx.x) >> 5;
    int lane  = threadIdx.x & 31;
    if (gwarp >= T_TOKENS) return;

    const float* xr = x + (size_t)gwarp * D_MODEL;
    float acc[NE];
#pragma unroll
    for (int e = 0; e < NE; e++) acc[e] = 0.f;
    for (int k = lane; k < D_MODEL; k += 32) {
        float xv = xr[k];
#pragma unroll
        for (int e = 0; e < NE; e++) acc[e] += xv * gate_w[e * D_MODEL + k];
    }
#pragma unroll
    for (int off = 16; off > 0; off >>= 1)
#pragma unroll
        for (int e = 0; e < NE; e++)
            acc[e] += __shfl_xor_sync(0xffffffffu, acc[e], off);

    if (lane == 0) {
        int i0 = 0; float b0 = acc[0];
#pragma unroll
        for (int i = 1; i < NE; i++) if (acc[i] > b0) { b0 = acc[i]; i0 = i; }
        int i1 = -1; float b1 = -3.0e38f;
#pragma unroll
        for (int i = 0; i < NE; i++)
            if (i != i0 && acc[i] > b1) { b1 = acc[i]; i1 = i; }
        float e1  = expf(b1 - b0);
        float inv = 1.f / (1.f + e1);
        g_topk_idx[gwarp][0] = i0;  g_topk_idx[gwarp][1] = i1;
        g_topk_w[gwarp][0]   = inv; g_topk_w[gwarp][1]   = e1 * inv;
        atomicAdd(&g_count[i0], 1);
        atomicAdd(&g_count[i1], 1);
    }
}

__global__ void offs_kernel() {
    if (threadIdx.x == 0 && blockIdx.x == 0) {
        int off = 0, toff = 0;
        for (int e = 0; e < NE; e++) {
            g_offs[e] = off; g_tile_offs[e] = toff;
            off  += g_count[e];
            toff += (g_count[e] + BM - 1) >> 7;
        }
        g_offs[NE] = off; g_tile_offs[NE] = toff;
    }
}

__global__ void compact_kernel() {
    int e   = blockIdx.x;
    int tid = threadIdx.x;
    __shared__ int s[1024];
    int base = g_offs[e];
    int run  = 0;
    for (int c0 = 0; c0 < T_TOKENS; c0 += 1024) {
        int t = c0 + tid;
        int sel = 0, slot = 0; float w = 0.f;
        if (t < T_TOKENS) {
            int i0 = g_topk_idx[t][0], i1 = g_topk_idx[t][1];
            if (i0 == e)      { sel = 1; slot = 0; w = g_topk_w[t][0]; }
            else if (i1 == e) { sel = 1; slot = 1; w = g_topk_w[t][1]; }
        }
        s[tid] = sel; __syncthreads();
        for (int d = 1; d < 1024; d <<= 1) {
            int v = (tid >= d) ? s[tid - d] : 0;
            __syncthreads();
            s[tid] += v;
            __syncthreads();
        }
        int incl  = s[tid];
        int total = s[1023];
        if (sel) {
            int r = base + run + incl - 1;
            g_list_token[r] = t;
            g_list_slot[r]  = slot;
            g_list_coef[r]  = w;
        }
        run += total;
        __syncthreads();
    }
}

// ---------------- UP GEMM (fused): g_A = silu(X Wg^T) * (X Wu^T) -------------
// grid (64 n-tiles of 64 over HALF_FFN, 136 m-tiles), band-swizzled (8 m-tiles).
// B stage: rows 0..63 = Wg rows, rows 64..127 = Wu rows. 2 CTAs per SM.
__global__ void __launch_bounds__(256, 2)
up_gemm() {
    const int tiles_n = 64;
    int b    = blockIdx.y * tiles_n + blockIdx.x;
    int band = b / (8 * tiles_n);
    int rem  = b % (8 * tiles_n);
    int mt   = band * 8 + (rem & 7);
    int nt   = rem >> 3;
    if (mt >= g_tile_offs[NE]) return;

    int e  = find_expert(mt);
    int m0 = (mt - g_tile_offs[e]) * BM;
    int rows = g_count[e] - m0; if (rows > BM) rows = BM;
    int base = g_offs[e];
    int n0   = nt * 64;
    int tid  = threadIdx.x, wid = tid >> 5;

    __shared__ int s_tok[BM];
    extern __shared__ __align__(16) char dyn[];
    uint32_t dbase = su32(dyn);

    if (tid < BM) {
        int rr = (tid < rows) ? tid : (rows - 1);
        s_tok[tid] = g_list_token[base + m0 + rr];
    }
    __syncthreads();

    const __half* we = g_wuh + (size_t)e * FFN_DIM * D_MODEL;
    int r0 = tid >> 3, q = tid & 7;
    const char* ap[4];
    const char* bp[4];
    uint32_t da[4], dbw[4];
#pragma unroll
    for (int p = 0; p < 4; p++) {
        int r = r0 + 32 * p;
        ap[p] = (const char*)(g_xh + (size_t)s_tok[r] * D_MODEL) + q * 16;
        int brow = (p < 2) ? (n0 + r) : (HALF_FFN + n0 + (r - 64));
        bp[p] = (const char*)(we + (size_t)brow * D_MODEL) + q * 16;
        da[p]  = (uint32_t)(r * (LDSH * 2) + q * 16);
        dbw[p] = (uint32_t)(BM * (LDSH * 2) + r * (LDSH * 2) + q * 16);
    }

    int wm = (wid & 3) * 32;          // 4 m-strips of 32
    int wn = (wid >> 2) * 32;         // 2 n-strips of 32

    FragC accg[2][2], accu[2][2];
#pragma unroll
    for (int i = 0; i < 2; i++)
#pragma unroll
        for (int j = 0; j < 2; j++) {
            wmma::fill_fragment(accg[i][j], 0.f);
            wmma::fill_fragment(accu[i][j], 0.f);
        }

    const int KT = D_MODEL / BKH;     // 32

#define UP_ISSUE(J) do {                                                     \
    uint32_t sb = dbase + ((J) % DEPTH) * STAGE_B;                           \
    size_t ko = (size_t)(J) * 128;                                           \
    _Pragma("unroll")                                                        \
    for (int p = 0; p < 4; p++) {                                            \
        cp16(sb + da[p],  ap[p] + ko);                                       \
        cp16(sb + dbw[p], bp[p] + ko);                                       \
    }                                                                        \
    cpcommit();                                                              \
} while (0)

    UP_ISSUE(0);
    UP_ISSUE(1);

#pragma unroll 1
    for (int kt = 0; kt < KT; kt++) {
        int jn = kt + DEPTH - 1;
        if (jn < KT) { UP_ISSUE(jn); } else { cpcommit(); }
        cpwait2();
        __syncthreads();

        __half* As = (__half*)(dyn + (kt % DEPTH) * STAGE_B);
        __half* Bs = As + BM * LDSH;
#pragma unroll
        for (int ks = 0; ks < BKH / 16; ks++) {
            FragA af[2];
#pragma unroll
            for (int i = 0; i < 2; i++)
                wmma::load_matrix_sync(af[i], As + (wm + i * 16) * LDSH + ks * 16, LDSH);
#pragma unroll
            for (int j = 0; j < 2; j++) {
                FragB bb;
                wmma::load_matrix_sync(bb, Bs + (wn + j * 16) * LDSH + ks * 16, LDSH);
                wmma::mma_sync(accg[0][j], af[0], bb, accg[0][j]);
                wmma::mma_sync(accg[1][j], af[1], bb, accg[1][j]);
                wmma::load_matrix_sync(bb, Bs + (64 + wn + j * 16) * LDSH + ks * 16, LDSH);
                wmma::mma_sync(accu[0][j], af[0], bb, accu[0][j]);
                wmma::mma_sync(accu[1][j], af[1], bb, accu[1][j]);
            }
        }
        __syncthreads();
    }
#undef UP_ISSUE

    // epilogue: silu(Cg)*Cu -> g_A (fp16)   (Cg, Cu staged in smem, fp32)
    float* Cg = (float*)dyn;
    float* Cu = Cg + 128 * 64;
#pragma unroll
    for (int i = 0; i < 2; i++)
#pragma unroll
        for (int j = 0; j < 2; j++) {
            wmma::store_matrix_sync(Cg + (wm + i * 16) * 64 + wn + j * 16,
                                    accg[i][j], 64, wmma::mem_row_major);
            wmma::store_matrix_sync(Cu + (wm + i * 16) * 64 + wn + j * 16,
                                    accu[i][j], 64, wmma::mem_row_major);
        }
    __syncthreads();

#pragma unroll
    for (int it = 0; it < 8; it++) {
        int idx = tid + it * 256;
        int row = idx >> 4;
        int col = (idx & 15) * 4;
        if (row < rows) {
            float4 g = *(const float4*)(Cg + row * 64 + col);
            float4 u = *(const float4*)(Cu + row * 64 + col);
            __half2 h0 = __floats2half2_rn(silu_mul(g.x, u.x), silu_mul(g.y, u.y));
            __half2 h1 = __floats2half2_rn(silu_mul(g.z, u.z), silu_mul(g.w, u.w));
            __half2* dst = (__half2*)(g_A + (size_t)(base + m0 + row) * HALF_FFN
                                          + n0 + col);
            dst[0] = h0; dst[1] = h1;
        }
    }
}

// ---------------- DOWN GEMM: g_Y[slot] = coef * (g_A Wdown^T) ----------------
// grid (16 n-tiles of 128 over D_MODEL, 136 m-tiles), same band swizzle.
__global__ void __launch_bounds__(256, 2)
down_gemm() {
    const int tiles_n = 16;
    int b    = blockIdx.y * tiles_n + blockIdx.x;
    int band = b / (8 * tiles_n);
    int rem  = b % (8 * tiles_n);
    int mt   = band * 8 + (rem & 7);
    int nt   = rem >> 3;
    if (mt >= g_tile_offs[NE]) return;

    int e  = find_expert(mt);
    int m0 = (mt - g_tile_offs[e]) * BM;
    int rows = g_count[e] - m0; if (rows > BM) rows = BM;
    int base = g_offs[e];
    int n0   = nt * 128;
    int tid  = threadIdx.x, wid = tid >> 5;

    __shared__ int   s_tk[BM];
    __shared__ int   s_sl[BM];
    __shared__ float s_cf[BM];
    extern __shared__ __align__(16) char dyn[];
    uint32_t dbase = su32(dyn);

    if (tid < BM) {
        if (tid < rows) {
            s_tk[tid] = g_list_token[base + m0 + tid];
            s_sl[tid] = g_list_slot[base + m0 + tid];
            s_cf[tid] = g_list_coef[base + m0 + tid];
        } else { s_tk[tid] = 0; s_sl[tid] = 0; s_cf[tid] = 0.f; }
    }
    __syncthreads();

    const __half* we = g_wdh + (size_t)e * D_MODEL * HALF_FFN;
    int r0 = tid >> 3, q = tid & 7;
    const char* ap[4];
    const char* bp[4];
    uint32_t da[4], dbw[4];
#pragma unroll
    for (int p = 0; p < 4; p++) {
        int r = r0 + 32 * p;
        int ar = (r < rows) ? r : (rows - 1);
        ap[p] = (const char*)(g_A + (size_t)(base + m0 + ar) * HALF_FFN) + q * 16;
        bp[p] = (const char*)(we + (size_t)(n0 + r) * HALF_FFN) + q * 16;
        da[p]  = (uint32_t)(r * (LDSH * 2) + q * 16);
        dbw[p] = (uint32_t)(BM * (LDSH * 2) + r * (LDSH * 2) + q * 16);
    }

    int wm = (wid & 3) * 32;          // 4 m-strips of 32
    int wn = (wid >> 2) * 64;         // 2 n-strips of 64

    FragC acc[2][4];
#pragma unroll
    for (int i = 0; i < 2; i++)
#pragma unroll
        for (int j = 0; j < 4; j++) wmma::fill_fragment(acc[i][j], 0.f);

    const int KT = HALF_FFN / BKH;    // 64

#define DN_ISSUE(J) do {                                                     \
    uint32_t sb = dbase + ((J) % DEPTH) * STAGE_B;                           \
    size_t ko = (size_t)(J) * 128;                                           \
    _Pragma("unroll")                                                        \
    for (int p = 0; p < 4; p++) {                                            \
        cp16(sb + da[p],  ap[p] + ko);                                       \
        cp16(sb + dbw[p], bp[p] + ko);                                       \
    }                                                                        \
    cpcommit();                                                              \
} while (0)

    DN_ISSUE(0);
    DN_ISSUE(1);

#pragma unroll 1
    for (int kt = 0; kt < KT; kt++) {
        int jn = kt + DEPTH - 1;
        if (jn < KT) { DN_ISSUE(jn); } else { cpcommit(); }
        cpwait2();
        __syncthreads();

        __half* As = (__half*)(dyn + (kt % DEPTH) * STAGE_B);
        __half* Bs = As + BM * LDSH;
#pragma unroll
        for (int ks = 0; ks < BKH / 16; ks++) {
            FragA af[2];
#pragma unroll
            for (int i = 0; i < 2; i++)
                wmma::load_matrix_sync(af[i], As + (wm + i * 16) * LDSH + ks * 16, LDSH);
#pragma unroll
            for (int j = 0; j < 4; j++) {
                FragB bb;
                wmma::load_matrix_sync(bb, Bs + (wn + j * 16) * LDSH + ks * 16, LDSH);
                wmma::mma_sync(acc[0][j], af[0], bb, acc[0][j]);
                wmma::mma_sync(acc[1][j], af[1], bb, acc[1][j]);
            }
        }
        __syncthreads();
    }
#undef DN_ISSUE

    // epilogue: scale by coef, scatter to g_Y (C staged in smem, 64 KB)
    float* Cs = (float*)dyn;
#pragma unroll
    for (int i = 0; i < 2; i++)
#pragma unroll
        for (int j = 0; j < 4; j++)
            wmma::store_matrix_sync(Cs + (wm + i * 16) * 128 + wn + j * 16,
                                    acc[i][j], 128, wmma::mem_row_major);
    __syncthreads();

#pragma unroll
    for (int it = 0; it < 16; it++) {
        int idx = tid + it * 256;
        int row = idx >> 5;
        int col = (idx & 31) * 4;
        if (row < rows) {
            float c = s_cf[row];
            float4 v = *(const float4*)(Cs + row * 128 + col);
            v.x *= c; v.y *= c; v.z *= c; v.w *= c;
            *(float4*)(g_Y + ((size_t)s_sl[row] * T_TOKENS + s_tk[row]) * D_MODEL
                           + n0 + col) = v;
        }
    }
}

__global__ void combine_kernel(float* __restrict__ out) {
    size_t i = (size_t)blockIdx.x * blockDim.x + threadIdx.x;
    const size_t n4 = (size_t)T_TOKENS * D_MODEL / 4;
    if (i < n4) {
        const float4* y = (const float4*)g_Y;
        float4 a = y[i], b = y[i + n4];
        float4 r;
        r.x = a.x + b.x; r.y = a.y + b.y; r.z = a.z + b.z; r.w = a.w + b.w;
        ((float4*)out)[i] = r;
    }
}

// ---------------- host entry -------------------------------------------------
extern "C" void kernel_launch(void* const* d_in, const int* in_sizes, int n_in,
                              void* d_out, int out_size) {
    const float* x      = (const float*)d_in[0];
    const float* gate_w = (const float*)d_in[1];
    const float* w_up   = (const float*)d_in[2];
    const float* w_down = (const float*)d_in[3];
    float* out = (float*)d_out;

    cudaFuncSetAttribute(up_gemm,   cudaFuncAttributeMaxDynamicSharedMemorySize, DYN_SMEM);
    cudaFuncSetAttribute(down_gemm, cudaFuncAttributeMaxDynamicSharedMemorySize, DYN_SMEM);

    void* d_xh;  cudaGetSymbolAddress(&d_xh,  g_xh);
    void* d_wuh; cudaGetSymbolAddress(&d_wuh, g_wuh);
    void* d_wdh; cudaGetSymbolAddress(&d_wdh, g_wdh);

    reset_kernel<<<1, 32>>>();
    routing_kernel<<<T_TOKENS / 8, 256>>>(x, gate_w);   // routing uses raw fp32 x
    offs_kernel<<<1, 1>>>();
    compact_kernel<<<NE, 1024>>>();

    // one-time fp32 -> fp16 conversion (halves all downstream GEMM traffic)
    cvt_kernel<<<1184, 256>>>((const float4*)x,      (uint2*)d_xh,
                              T_TOKENS * D_MODEL / 4);
    cvt_kernel<<<1184, 256>>>((const float4*)w_up,   (uint2*)d_wuh,
                              NE * FFN_DIM * D_MODEL / 4);
    cvt_kernel<<<1184, 256>>>((const float4*)w_down, (uint2*)d_wdh,
                              NE * D_MODEL * HALF_FFN / 4);

    // up: 64 n-tiles (64 cols of HALF_FFN each, g+u) x 136 m-tiles
    up_gemm<<<dim3(64, 136, 1), 256, DYN_SMEM>>>();
    // down: 16 n-tiles (128 cols of D_MODEL) x 136 m-tiles
    down_gemm<<<dim3(16, 136, 1), 256, DYN_SMEM>>>();

    combine_kernel<<<(T_TOKENS * D_MODEL / 4 + 255) / 256, 256>>>(out);
}

// round 12
// speedup vs baseline: 5.6322x; 1.0012x over previous
#include <cuda_runtime.h>
#include <cuda_fp16.h>
#include <mma.h>
#include <cstdint>

using namespace nvcuda;

#define D_MODEL   2048
#define FFN_DIM   8192
#define HALF_FFN  4096
#define NE        8
#define T_TOKENS  8192
#define MAXROWS   (T_TOKENS * 2)

#define BM 128
#define BKH 64                         // k elements per tile (fp16) = 128 B/row
#define LDSH 72                        // 64 + 8 pad halfs per smem row (144 B)
#define DEPTH 3
#define MBAND 16                       // m-tiles per swizzle band (~1 expert)
#define MT_PAD 144                     // grid.y padded to multiple of MBAND
#define STAGE_B (256 * LDSH * 2)       // A(128 rows) + B(128 rows) = 36864 B
#define DYN_SMEM (DEPTH * STAGE_B)     // 110592 B; 2 CTAs/SM

// ---------------- scratch (device globals; no runtime allocation) ----------
__device__ __half g_xh [(size_t)T_TOKENS * D_MODEL];        // 32 MB fp16 x
__device__ __half g_wuh[(size_t)NE * FFN_DIM * D_MODEL];    // 384 MB fp16 w_up
__device__ __half g_wdh[(size_t)NE * D_MODEL * HALF_FFN];   // 192 MB fp16 w_down
__device__ __half g_A  [(size_t)MAXROWS * HALF_FFN];        // 128 MB fp16 activated
__device__ float  g_Y  [(size_t)2 * T_TOKENS * D_MODEL];    // 128 MB per-slot outputs
__device__ int    g_topk_idx[T_TOKENS][2];
__device__ float  g_topk_w[T_TOKENS][2];
__device__ int    g_count[NE];
__device__ int    g_offs[NE + 1];
__device__ int    g_tile_offs[NE + 1];
__device__ int    g_list_token[MAXROWS];
__device__ int    g_list_slot[MAXROWS];
__device__ float  g_list_coef[MAXROWS];

// ---------------- PTX helpers ------------------------------------------------
__device__ __forceinline__ uint32_t su32(const void* p) {
    uint32_t r;
    asm("{ .reg .u64 t; cvta.to.shared.u64 t, %1; cvt.u32.u64 %0, t; }"
        : "=r"(r) : "l"(p));
    return r;
}
__device__ __forceinline__ void cp16(uint32_t d, const void* s) {
    asm volatile("cp.async.cg.shared.global [%0], [%1], 16;\n"
                 :: "r"(d), "l"(s) : "memory");
}
__device__ __forceinline__ void cpcommit() {
    asm volatile("cp.async.commit_group;\n" ::: "memory");
}
__device__ __forceinline__ void cpwait2() {
    asm volatile("cp.async.wait_group 2;\n" ::: "memory");
}

// ---------------- FP16 wmma types (fp32 accumulate) --------------------------
using FragA = wmma::fragment<wmma::matrix_a, 16, 16, 16, __half, wmma::row_major>;
using FragB = wmma::fragment<wmma::matrix_b, 16, 16, 16, __half, wmma::col_major>;
using FragC = wmma::fragment<wmma::accumulator, 16, 16, 16, float>;

__device__ __forceinline__ int find_expert(int ytile) {
    int e = 0;
#pragma unroll
    for (int i = 0; i < NE; i++) if (ytile >= g_tile_offs[i + 1]) e = i + 1;
    return e;
}

__device__ __forceinline__ float silu_mul(float g, float u) {
    return g * (1.f / (1.f + __expf(-g))) * u;
}

// ---------------- fp32 -> fp16 conversion of both weights (one launch) -------
__global__ void cvt_w_kernel(const float4* __restrict__ s1, uint2* __restrict__ d1,
                             int n1,
                             const float4* __restrict__ s2, uint2* __restrict__ d2,
                             int n2) {
    int i = blockIdx.x * blockDim.x + threadIdx.x;
    int stride = gridDim.x * blockDim.x;
    int nt = n1 + n2;
    for (; i < nt; i += stride) {
        const float4* s; uint2* d; int j;
        if (i < n1) { s = s1; d = d1; j = i; }
        else        { s = s2; d = d2; j = i - n1; }
        float4 v = s[j];
        __half2 a = __floats2half2_rn(v.x, v.y);
        __half2 b = __floats2half2_rn(v.z, v.w);
        uint2 o;
        o.x = *(const uint32_t*)&a;
        o.y = *(const uint32_t*)&b;
        d[j] = o;
    }
}

// ---------------- routing (also emits fp16 copy of x) ------------------------
__global__ void reset_kernel() {
    if (threadIdx.x < NE) g_count[threadIdx.x] = 0;
}

__global__ void routing_kernel(const float* __restrict__ x,
                               const float* __restrict__ gate_w) {
    int gwarp = (blockIdx.x * blockDim.x + threadIdx.x) >> 5;
    int lane  = threadIdx.x & 31;
    if (gwarp >= T_TOKENS) return;

    const float* xr = x + (size_t)gwarp * D_MODEL;
    __half* xh = g_xh + (size_t)gwarp * D_MODEL;
    float acc[NE];
#pragma unroll
    for (int e = 0; e < NE; e++) acc[e] = 0.f;
    for (int k = lane; k < D_MODEL; k += 32) {
        float xv = xr[k];
        xh[k] = __float2half_rn(xv);           // fused fp16 conversion of x
#pragma unroll
        for (int e = 0; e < NE; e++) acc[e] += xv * gate_w[e * D_MODEL + k];
    }
#pragma unroll
    for (int off = 16; off > 0; off >>= 1)
#pragma unroll
        for (int e = 0; e < NE; e++)
            acc[e] += __shfl_xor_sync(0xffffffffu, acc[e], off);

    if (lane == 0) {
        int i0 = 0; float b0 = acc[0];
#pragma unroll
        for (int i = 1; i < NE; i++) if (acc[i] > b0) { b0 = acc[i]; i0 = i; }
        int i1 = -1; float b1 = -3.0e38f;
#pragma unroll
        for (int i = 0; i < NE; i++)
            if (i != i0 && acc[i] > b1) { b1 = acc[i]; i1 = i; }
        float e1  = expf(b1 - b0);
        float inv = 1.f / (1.f + e1);
        g_topk_idx[gwarp][0] = i0;  g_topk_idx[gwarp][1] = i1;
        g_topk_w[gwarp][0]   = inv; g_topk_w[gwarp][1]   = e1 * inv;
        atomicAdd(&g_count[i0], 1);
        atomicAdd(&g_count[i1], 1);
    }
}

__global__ void offs_kernel() {
    if (threadIdx.x == 0 && blockIdx.x == 0) {
        int off = 0, toff = 0;
        for (int e = 0; e < NE; e++) {
            g_offs[e] = off; g_tile_offs[e] = toff;
            off  += g_count[e];
            toff += (g_count[e] + BM - 1) >> 7;
        }
        g_offs[NE] = off; g_tile_offs[NE] = toff;
    }
}

__global__ void compact_kernel() {
    int e   = blockIdx.x;
    int tid = threadIdx.x;
    __shared__ int s[1024];
    int base = g_offs[e];
    int run  = 0;
    for (int c0 = 0; c0 < T_TOKENS; c0 += 1024) {
        int t = c0 + tid;
        int sel = 0, slot = 0; float w = 0.f;
        if (t < T_TOKENS) {
            int i0 = g_topk_idx[t][0], i1 = g_topk_idx[t][1];
            if (i0 == e)      { sel = 1; slot = 0; w = g_topk_w[t][0]; }
            else if (i1 == e) { sel = 1; slot = 1; w = g_topk_w[t][1]; }
        }
        s[tid] = sel; __syncthreads();
        for (int d = 1; d < 1024; d <<= 1) {
            int v = (tid >= d) ? s[tid - d] : 0;
            __syncthreads();
            s[tid] += v;
            __syncthreads();
        }
        int incl  = s[tid];
        int total = s[1023];
        if (sel) {
            int r = base + run + incl - 1;
            g_list_token[r] = t;
            g_list_slot[r]  = slot;
            g_list_coef[r]  = w;
        }
        run += total;
        __syncthreads();
    }
}

// ---------------- UP GEMM (fused): g_A = silu(X Wg^T) * (X Wu^T) -------------
// grid (64 n-tiles of 64 over HALF_FFN, MT_PAD m-tiles). Band swizzle of
// MBAND=16 m-tiles; MT_PAD is a multiple of MBAND so every band is complete
// (the R11 bug was a truncated last band leaving g_A columns unwritten).
// B stage: rows 0..63 = Wg rows, rows 64..127 = Wu rows. 2 CTAs per SM.
__global__ void __launch_bounds__(256, 2)
up_gemm() {
    const int tiles_n = 64;
    int b    = blockIdx.y * tiles_n + blockIdx.x;
    int band = b / (MBAND * tiles_n);
    int rem  = b % (MBAND * tiles_n);
    int mt   = band * MBAND + (rem & (MBAND - 1));
    int nt   = rem >> 4;
    if (mt >= g_tile_offs[NE]) return;

    int e  = find_expert(mt);
    int m0 = (mt - g_tile_offs[e]) * BM;
    int rows = g_count[e] - m0; if (rows > BM) rows = BM;
    int base = g_offs[e];
    int n0   = nt * 64;
    int tid  = threadIdx.x, wid = tid >> 5;

    __shared__ int s_tok[BM];
    extern __shared__ __align__(16) char dyn[];
    uint32_t dbase = su32(dyn);

    if (tid < BM) {
        int rr = (tid < rows) ? tid : (rows - 1);
        s_tok[tid] = g_list_token[base + m0 + rr];
    }
    __syncthreads();

    const __half* we = g_wuh + (size_t)e * FFN_DIM * D_MODEL;
    int r0 = tid >> 3, q = tid & 7;
    const char* ap[4];
    const char* bp[4];
    uint32_t da[4], dbw[4];
#pragma unroll
    for (int p = 0; p < 4; p++) {
        int r = r0 + 32 * p;
        ap[p] = (const char*)(g_xh + (size_t)s_tok[r] * D_MODEL) + q * 16;
        int brow = (p < 2) ? (n0 + r) : (HALF_FFN + n0 + (r - 64));
        bp[p] = (const char*)(we + (size_t)brow * D_MODEL) + q * 16;
        da[p]  = (uint32_t)(r * (LDSH * 2) + q * 16);
        dbw[p] = (uint32_t)(BM * (LDSH * 2) + r * (LDSH * 2) + q * 16);
    }

    int wm = (wid & 3) * 32;          // 4 m-strips of 32
    int wn = (wid >> 2) * 32;         // 2 n-strips of 32

    FragC accg[2][2], accu[2][2];
#pragma unroll
    for (int i = 0; i < 2; i++)
#pragma unroll
        for (int j = 0; j < 2; j++) {
            wmma::fill_fragment(accg[i][j], 0.f);
            wmma::fill_fragment(accu[i][j], 0.f);
        }

    const int KT = D_MODEL / BKH;     // 32

#define UP_ISSUE(J) do {                                                     \
    uint32_t sb = dbase + ((J) % DEPTH) * STAGE_B;                           \
    size_t ko = (size_t)(J) * 128;                                           \
    _Pragma("unroll")                                                        \
    for (int p = 0; p < 4; p++) {                                            \
        cp16(sb + da[p],  ap[p] + ko);                                       \
        cp16(sb + dbw[p], bp[p] + ko);                                       \
    }                                                                        \
    cpcommit();                                                              \
} while (0)

    UP_ISSUE(0);
    UP_ISSUE(1);

#pragma unroll 1
    for (int kt = 0; kt < KT; kt++) {
        int jn = kt + DEPTH - 1;
        if (jn < KT) { UP_ISSUE(jn); } else { cpcommit(); }
        cpwait2();
        __syncthreads();

        __half* As = (__half*)(dyn + (kt % DEPTH) * STAGE_B);
        __half* Bs = As + BM * LDSH;
#pragma unroll
        for (int ks = 0; ks < BKH / 16; ks++) {
            FragA af[2];
#pragma unroll
            for (int i = 0; i < 2; i++)
                wmma::load_matrix_sync(af[i], As + (wm + i * 16) * LDSH + ks * 16, LDSH);
#pragma unroll
            for (int j = 0; j < 2; j++) {
                FragB bb;
                wmma::load_matrix_sync(bb, Bs + (wn + j * 16) * LDSH + ks * 16, LDSH);
                wmma::mma_sync(accg[0][j], af[0], bb, accg[0][j]);
                wmma::mma_sync(accg[1][j], af[1], bb, accg[1][j]);
                wmma::load_matrix_sync(bb, Bs + (64 + wn + j * 16) * LDSH + ks * 16, LDSH);
                wmma::mma_sync(accu[0][j], af[0], bb, accu[0][j]);
                wmma::mma_sync(accu[1][j], af[1], bb, accu[1][j]);
            }
        }
        __syncthreads();
    }
#undef UP_ISSUE

    // epilogue: silu(Cg)*Cu -> g_A (fp16)   (Cg, Cu staged in smem, fp32)
    float* Cg = (float*)dyn;
    float* Cu = Cg + 128 * 64;
#pragma unroll
    for (int i = 0; i < 2; i++)
#pragma unroll
        for (int j = 0; j < 2; j++) {
            wmma::store_matrix_sync(Cg + (wm + i * 16) * 64 + wn + j * 16,
                                    accg[i][j], 64, wmma::mem_row_major);
            wmma::store_matrix_sync(Cu + (wm + i * 16) * 64 + wn + j * 16,
                                    accu[i][j], 64, wmma::mem_row_major);
        }
    __syncthreads();

#pragma unroll
    for (int it = 0; it < 8; it++) {
        int idx = tid + it * 256;
        int row = idx >> 4;
        int col = (idx & 15) * 4;
        if (row < rows) {
            float4 g = *(const float4*)(Cg + row * 64 + col);
            float4 u = *(const float4*)(Cu + row * 64 + col);
            __half2 h0 = __floats2half2_rn(silu_mul(g.x, u.x), silu_mul(g.y, u.y));
            __half2 h1 = __floats2half2_rn(silu_mul(g.z, u.z), silu_mul(g.w, u.w));
            __half2* dst = (__half2*)(g_A + (size_t)(base + m0 + row) * HALF_FFN
                                          + n0 + col);
            dst[0] = h0; dst[1] = h1;
        }
    }
}

// ---------------- DOWN GEMM: g_Y[slot] = coef * (g_A Wdown^T) ----------------
// grid (16 n-tiles of 128 over D_MODEL, MT_PAD m-tiles), same complete bands.
__global__ void __launch_bounds__(256, 2)
down_gemm() {
    const int tiles_n = 16;
    int b    = blockIdx.y * tiles_n + blockIdx.x;
    int band = b / (MBAND * tiles_n);
    int rem  = b % (MBAND * tiles_n);
    int mt   = band * MBAND + (rem & (MBAND - 1));
    int nt   = rem >> 4;
    if (mt >= g_tile_offs[NE]) return;

    int e  = find_expert(mt);
    int m0 = (mt - g_tile_offs[e]) * BM;
    int rows = g_count[e] - m0; if (rows > BM) rows = BM;
    int base = g_offs[e];
    int n0   = nt * 128;
    int tid  = threadIdx.x, wid = tid >> 5;

    __shared__ int   s_tk[BM];
    __shared__ int   s_sl[BM];
    __shared__ float s_cf[BM];
    extern __shared__ __align__(16) char dyn[];
    uint32_t dbase = su32(dyn);

    if (tid < BM) {
        if (tid < rows) {
            s_tk[tid] = g_list_token[base + m0 + tid];
            s_sl[tid] = g_list_slot[base + m0 + tid];
            s_cf[tid] = g_list_coef[base + m0 + tid];
        } else { s_tk[tid] = 0; s_sl[tid] = 0; s_cf[tid] = 0.f; }
    }
    __syncthreads();

    const __half* we = g_wdh + (size_t)e * D_MODEL * HALF_FFN;
    int r0 = tid >> 3, q = tid & 7;
    const char* ap[4];
    const char* bp[4];
    uint32_t da[4], dbw[4];
#pragma unroll
    for (int p = 0; p < 4; p++) {
        int r = r0 + 32 * p;
        int ar = (r < rows) ? r : (rows - 1);
        ap[p] = (const char*)(g_A + (size_t)(base + m0 + ar) * HALF_FFN) + q * 16;
        bp[p] = (const char*)(we + (size_t)(n0 + r) * HALF_FFN) + q * 16;
        da[p]  = (uint32_t)(r * (LDSH * 2) + q * 16);
        dbw[p] = (uint32_t)(BM * (LDSH * 2) + r * (LDSH * 2) + q * 16);
    }

    int wm = (wid & 3) * 32;          // 4 m-strips of 32
    int wn = (wid >> 2) * 64;         // 2 n-strips of 64

    FragC acc[2][4];
#pragma unroll
    for (int i = 0; i < 2; i++)
#pragma unroll
        for (int j = 0; j < 4; j++) wmma::fill_fragment(acc[i][j], 0.f);

    const int KT = HALF_FFN / BKH;    // 64

#define DN_ISSUE(J) do {                                                     \
    uint32_t sb = dbase + ((J) % DEPTH) * STAGE_B;                           \
    size_t ko = (size_t)(J) * 128;                                           \
    _Pragma("unroll")                                                        \
    for (int p = 0; p < 4; p++) {                                            \
        cp16(sb + da[p],  ap[p] + ko);                                       \
        cp16(sb + dbw[p], bp[p] + ko);                                       \
    }                                                                        \
    cpcommit();                                                              \
} while (0)

    DN_ISSUE(0);
    DN_ISSUE(1);

#pragma unroll 1
    for (int kt = 0; kt < KT; kt++) {
        int jn = kt + DEPTH - 1;
        if (jn < KT) { DN_ISSUE(jn); } else { cpcommit(); }
        cpwait2();
        __syncthreads();

        __half* As = (__half*)(dyn + (kt % DEPTH) * STAGE_B);
        __half* Bs = As + BM * LDSH;
#pragma unroll
        for (int ks = 0; ks < BKH / 16; ks++) {
            FragA af[2];
#pragma unroll
            for (int i = 0; i < 2; i++)
                wmma::load_matrix_sync(af[i], As + (wm + i * 16) * LDSH + ks * 16, LDSH);
#pragma unroll
            for (int j = 0; j < 4; j++) {
                FragB bb;
                wmma::load_matrix_sync(bb, Bs + (wn + j * 16) * LDSH + ks * 16, LDSH);
                wmma::mma_sync(acc[0][j], af[0], bb, acc[0][j]);
                wmma::mma_sync(acc[1][j], af[1], bb, acc[1][j]);
            }
        }
        __syncthreads();
    }
#undef DN_ISSUE

    // epilogue: scale by coef, scatter to g_Y (C staged in smem, 64 KB)
    float* Cs = (float*)dyn;
#pragma unroll
    for (int i = 0; i < 2; i++)
#pragma unroll
        for (int j = 0; j < 4; j++)
            wmma::store_matrix_sync(Cs + (wm + i * 16) * 128 + wn + j * 16,
                                    acc[i][j], 128, wmma::mem_row_major);
    __syncthreads();

#pragma unroll
    for (int it = 0; it < 16; it++) {
        int idx = tid + it * 256;
        int row = idx >> 5;
        int col = (idx & 31) * 4;
        if (row < rows) {
            float c = s_cf[row];
            float4 v = *(const float4*)(Cs + row * 128 + col);
            v.x *= c; v.y *= c; v.z *= c; v.w *= c;
            *(float4*)(g_Y + ((size_t)s_sl[row] * T_TOKENS + s_tk[row]) * D_MODEL
                           + n0 + col) = v;
        }
    }
}

__global__ void combine_kernel(float* __restrict__ out) {
    size_t i = (size_t)blockIdx.x * blockDim.x + threadIdx.x;
    const size_t n4 = (size_t)T_TOKENS * D_MODEL / 4;
    if (i < n4) {
        const float4* y = (const float4*)g_Y;
        float4 a = y[i], b = y[i + n4];
        float4 r;
        r.x = a.x + b.x; r.y = a.y + b.y; r.z = a.z + b.z; r.w = a.w + b.w;
        ((float4*)out)[i] = r;
    }
}

// ---------------- host entry -------------------------------------------------
extern "C" void kernel_launch(void* const* d_in, const int* in_sizes, int n_in,
                              void* d_out, int out_size) {
    const float* x      = (const float*)d_in[0];
    const float* gate_w = (const float*)d_in[1];
    const float* w_up   = (const float*)d_in[2];
    const float* w_down = (const float*)d_in[3];
    float* out = (float*)d_out;

    cudaFuncSetAttribute(up_gemm,   cudaFuncAttributeMaxDynamicSharedMemorySize, DYN_SMEM);
    cudaFuncSetAttribute(down_gemm, cudaFuncAttributeMaxDynamicSharedMemorySize, DYN_SMEM);

    void* d_wuh; cudaGetSymbolAddress(&d_wuh, g_wuh);
    void* d_wdh; cudaGetSymbolAddress(&d_wdh, g_wdh);

    reset_kernel<<<1, 32>>>();
    routing_kernel<<<T_TOKENS / 8, 256>>>(x, gate_w);   // also writes g_xh (fp16)
    offs_kernel<<<1, 1>>>();
    compact_kernel<<<NE, 1024>>>();

    // one-time fp32 -> fp16 conversion of both weight tensors (single launch)
    cvt_w_kernel<<<1184, 256>>>((const float4*)w_up,   (uint2*)d_wuh,
                                NE * FFN_DIM * D_MODEL / 4,
                                (const float4*)w_down, (uint2*)d_wdh,
                                NE * D_MODEL * HALF_FFN / 4);

    // up: 64 n-tiles (64 cols of HALF_FFN each, g+u) x MT_PAD m-tiles
    up_gemm<<<dim3(64, MT_PAD, 1), 256, DYN_SMEM>>>();
    // down: 16 n-tiles (128 cols of D_MODEL) x MT_PAD m-tiles
    down_gemm<<<dim3(16, MT_PAD, 1), 256, DYN_SMEM>>>();

    combine_kernel<<<(T_TOKENS * D_MODEL / 4 + 255) / 256, 256>>>(out);
}

// round 13
// speedup vs baseline: 5.6938x; 1.0109x over previous
#include <cuda_runtime.h>
#include <cuda_fp16.h>
#include <mma.h>
#include <cstdint>

using namespace nvcuda;

#define D_MODEL   2048
#define FFN_DIM   8192
#define HALF_FFN  4096
#define NE        8
#define T_TOKENS  8192
#define MAXROWS   (T_TOKENS * 2)

#define BM 128
#define BKH 64                         // k elements per tile (fp16) = 128 B/row
#define LDSH 72                        // 64 + 8 pad halfs per smem row (144 B)
#define DEPTH 3
#define MBAND 16                       // m-tiles per swizzle band (~1 expert)
#define MT_PAD 144                     // GEMM m-tile rows (multiple of MBAND)
#define CVD 8                          // extra grid.y rows in up_gemm for w_down cvt
#define ROUTE_BLOCKS 1024              // routing blocks in phase1
#define CVTU_BLOCKS 1024               // w_up cvt blocks in phase1
#define STAGE_B (256 * LDSH * 2)       // A(128 rows) + B(128 rows) = 36864 B
#define DYN_SMEM (DEPTH * STAGE_B)     // 110592 B; 2 CTAs/SM

#define N4_WUP (NE * FFN_DIM * D_MODEL / 4)     // 33554432 float4
#define N4_WDN (NE * D_MODEL * HALF_FFN / 4)    // 16777216 float4

// ---------------- scratch (device globals; no runtime allocation) ----------
__device__ __half g_xh [(size_t)T_TOKENS * D_MODEL];        // 32 MB fp16 x
__device__ __half g_wuh[(size_t)NE * FFN_DIM * D_MODEL];    // 384 MB fp16 w_up
__device__ __half g_wdh[(size_t)NE * D_MODEL * HALF_FFN];   // 192 MB fp16 w_down
__device__ __half g_A  [(size_t)MAXROWS * HALF_FFN];        // 128 MB fp16 activated
__device__ float  g_Y  [(size_t)2 * T_TOKENS * D_MODEL];    // 128 MB per-slot outputs
__device__ int    g_topk_idx[T_TOKENS][2];
__device__ float  g_topk_w[T_TOKENS][2];
__device__ int    g_count[NE];
__device__ int    g_offs[NE + 1];
__device__ int    g_tile_offs[NE + 1];
__device__ int    g_list_token[MAXROWS];
__device__ int    g_list_slot[MAXROWS];
__device__ float  g_list_coef[MAXROWS];

// ---------------- PTX helpers ------------------------------------------------
__device__ __forceinline__ uint32_t su32(const void* p) {
    uint32_t r;
    asm("{ .reg .u64 t; cvta.to.shared.u64 t, %1; cvt.u32.u64 %0, t; }"
        : "=r"(r) : "l"(p));
    return r;
}
__device__ __forceinline__ void cp16(uint32_t d, const void* s) {
    asm volatile("cp.async.cg.shared.global [%0], [%1], 16;\n"
                 :: "r"(d), "l"(s) : "memory");
}
__device__ __forceinline__ void cpcommit() {
    asm volatile("cp.async.commit_group;\n" ::: "memory");
}
__device__ __forceinline__ void cpwait2() {
    asm volatile("cp.async.wait_group 2;\n" ::: "memory");
}

__device__ __forceinline__ void cvt4(const float4* __restrict__ s,
                                     uint2* __restrict__ d, int j) {
    float4 v = s[j];
    __half2 a = __floats2half2_rn(v.x, v.y);
    __half2 b = __floats2half2_rn(v.z, v.w);
    uint2 o;
    o.x = *(const uint32_t*)&a;
    o.y = *(const uint32_t*)&b;
    d[j] = o;
}

// ---------------- FP16 wmma types (fp32 accumulate) --------------------------
using FragA = wmma::fragment<wmma::matrix_a, 16, 16, 16, __half, wmma::row_major>;
using FragB = wmma::fragment<wmma::matrix_b, 16, 16, 16, __half, wmma::col_major>;
using FragC = wmma::fragment<wmma::accumulator, 16, 16, 16, float>;

__device__ __forceinline__ int find_expert(int ytile) {
    int e = 0;
#pragma unroll
    for (int i = 0; i < NE; i++) if (ytile >= g_tile_offs[i + 1]) e = i + 1;
    return e;
}

__device__ __forceinline__ float silu_mul(float g, float u) {
    return g * (1.f / (1.f + __expf(-g))) * u;
}

// ---------------- phase1: routing + fp16 cvt of x AND w_up (one launch) ------
__global__ void reset_kernel() {
    if (threadIdx.x < NE) g_count[threadIdx.x] = 0;
}

__global__ void phase1_kernel(const float* __restrict__ x,
                              const float* __restrict__ gate_w,
                              const float4* __restrict__ wu_src) {
    if (blockIdx.x >= ROUTE_BLOCKS) {
        // ---- w_up fp32 -> fp16 (grid-stride over CVTU_BLOCKS blocks) ----
        int i = (blockIdx.x - ROUTE_BLOCKS) * blockDim.x + threadIdx.x;
        int stride = CVTU_BLOCKS * blockDim.x;
        uint2* d = (uint2*)g_wuh;
        for (; i < N4_WUP; i += stride) cvt4(wu_src, d, i);
        return;
    }

    // ---- routing: one warp per token; also emits fp16 copy of x ----
    int gwarp = (blockIdx.x * blockDim.x + threadIdx.x) >> 5;
    int lane  = threadIdx.x & 31;
    if (gwarp >= T_TOKENS) return;

    const float* xr = x + (size_t)gwarp * D_MODEL;
    __half* xh = g_xh + (size_t)gwarp * D_MODEL;
    float acc[NE];
#pragma unroll
    for (int e = 0; e < NE; e++) acc[e] = 0.f;
    for (int k = lane; k < D_MODEL; k += 32) {
        float xv = xr[k];
        xh[k] = __float2half_rn(xv);
#pragma unroll
        for (int e = 0; e < NE; e++) acc[e] += xv * gate_w[e * D_MODEL + k];
    }
#pragma unroll
    for (int off = 16; off > 0; off >>= 1)
#pragma unroll
        for (int e = 0; e < NE; e++)
            acc[e] += __shfl_xor_sync(0xffffffffu, acc[e], off);

    if (lane == 0) {
        int i0 = 0; float b0 = acc[0];
#pragma unroll
        for (int i = 1; i < NE; i++) if (acc[i] > b0) { b0 = acc[i]; i0 = i; }
        int i1 = -1; float b1 = -3.0e38f;
#pragma unroll
        for (int i = 0; i < NE; i++)
            if (i != i0 && acc[i] > b1) { b1 = acc[i]; i1 = i; }
        float e1  = expf(b1 - b0);
        float inv = 1.f / (1.f + e1);
        g_topk_idx[gwarp][0] = i0;  g_topk_idx[gwarp][1] = i1;
        g_topk_w[gwarp][0]   = inv; g_topk_w[gwarp][1]   = e1 * inv;
        atomicAdd(&g_count[i0], 1);
        atomicAdd(&g_count[i1], 1);
    }
}

__global__ void offs_kernel() {
    if (threadIdx.x == 0 && blockIdx.x == 0) {
        int off = 0, toff = 0;
        for (int e = 0; e < NE; e++) {
            g_offs[e] = off; g_tile_offs[e] = toff;
            off  += g_count[e];
            toff += (g_count[e] + BM - 1) >> 7;
        }
        g_offs[NE] = off; g_tile_offs[NE] = toff;
    }
}

__global__ void compact_kernel() {
    int e   = blockIdx.x;
    int tid = threadIdx.x;
    __shared__ int s[1024];
    int base = g_offs[e];
    int run  = 0;
    for (int c0 = 0; c0 < T_TOKENS; c0 += 1024) {
        int t = c0 + tid;
        int sel = 0, slot = 0; float w = 0.f;
        if (t < T_TOKENS) {
            int i0 = g_topk_idx[t][0], i1 = g_topk_idx[t][1];
            if (i0 == e)      { sel = 1; slot = 0; w = g_topk_w[t][0]; }
            else if (i1 == e) { sel = 1; slot = 1; w = g_topk_w[t][1]; }
        }
        s[tid] = sel; __syncthreads();
        for (int d = 1; d < 1024; d <<= 1) {
            int v = (tid >= d) ? s[tid - d] : 0;
            __syncthreads();
            s[tid] += v;
            __syncthreads();
        }
        int incl  = s[tid];
        int total = s[1023];
        if (sel) {
            int r = base + run + incl - 1;
            g_list_token[r] = t;
            g_list_slot[r]  = slot;
            g_list_coef[r]  = w;
        }
        run += total;
        __syncthreads();
    }
}

// ---------------- UP GEMM (fused): g_A = silu(X Wg^T) * (X Wu^T) -------------
// grid (64 n-tiles, MT_PAD + CVD m-rows). Rows >= MT_PAD convert w_down to
// fp16 in the shadow of the tensor-bound GEMM waves (down_gemm launches after
// up_gemm completes, so ordering is guaranteed by the stream).
// B stage: rows 0..63 = Wg rows, rows 64..127 = Wu rows. 2 CTAs per SM.
__global__ void __launch_bounds__(256, 2)
up_gemm(const float4* __restrict__ wd_src) {
    const int tiles_n = 64;

    if (blockIdx.y >= MT_PAD) {
        // ---- w_down fp32 -> fp16 (grid-stride over CVD*64 blocks) ----
        int i = (((int)blockIdx.y - MT_PAD) * tiles_n + (int)blockIdx.x)
                    * (int)blockDim.x + (int)threadIdx.x;
        int stride = CVD * tiles_n * (int)blockDim.x;
        uint2* d = (uint2*)g_wdh;
        for (; i < N4_WDN; i += stride) cvt4(wd_src, d, i);
        return;
    }

    int b    = blockIdx.y * tiles_n + blockIdx.x;
    int band = b / (MBAND * tiles_n);
    int rem  = b % (MBAND * tiles_n);
    int mt   = band * MBAND + (rem & (MBAND - 1));
    int nt   = rem >> 4;
    if (mt >= g_tile_offs[NE]) return;

    int e  = find_expert(mt);
    int m0 = (mt - g_tile_offs[e]) * BM;
    int rows = g_count[e] - m0; if (rows > BM) rows = BM;
    int base = g_offs[e];
    int n0   = nt * 64;
    int tid  = threadIdx.x, wid = tid >> 5;

    __shared__ int s_tok[BM];
    extern __shared__ __align__(16) char dyn[];
    uint32_t dbase = su32(dyn);

    if (tid < BM) {
        int rr = (tid < rows) ? tid : (rows - 1);
        s_tok[tid] = g_list_token[base + m0 + rr];
    }
    __syncthreads();

    const __half* we = g_wuh + (size_t)e * FFN_DIM * D_MODEL;
    int r0 = tid >> 3, q = tid & 7;
    const char* ap[4];
    const char* bp[4];
    uint32_t da[4], dbw[4];
#pragma unroll
    for (int p = 0; p < 4; p++) {
        int r = r0 + 32 * p;
        ap[p] = (const char*)(g_xh + (size_t)s_tok[r] * D_MODEL) + q * 16;
        int brow = (p < 2) ? (n0 + r) : (HALF_FFN + n0 + (r - 64));
        bp[p] = (const char*)(we + (size_t)brow * D_MODEL) + q * 16;
        da[p]  = (uint32_t)(r * (LDSH * 2) + q * 16);
        dbw[p] = (uint32_t)(BM * (LDSH * 2) + r * (LDSH * 2) + q * 16);
    }

    int wm = (wid & 3) * 32;          // 4 m-strips of 32
    int wn = (wid >> 2) * 32;         // 2 n-strips of 32

    FragC accg[2][2], accu[2][2];
#pragma unroll
    for (int i = 0; i < 2; i++)
#pragma unroll
        for (int j = 0; j < 2; j++) {
            wmma::fill_fragment(accg[i][j], 0.f);
            wmma::fill_fragment(accu[i][j], 0.f);
        }

    const int KT = D_MODEL / BKH;     // 32

#define UP_ISSUE(J) do {                                                     \
    uint32_t sb = dbase + ((J) % DEPTH) * STAGE_B;                           \
    size_t ko = (size_t)(J) * 128;                                           \
    _Pragma("unroll")                                                        \
    for (int p = 0; p < 4; p++) {                                            \
        cp16(sb + da[p],  ap[p] + ko);                                       \
        cp16(sb + dbw[p], bp[p] + ko);                                       \
    }                                                                        \
    cpcommit();                                                              \
} while (0)

    UP_ISSUE(0);
    UP_ISSUE(1);

#pragma unroll 1
    for (int kt = 0; kt < KT; kt++) {
        int jn = kt + DEPTH - 1;
        if (jn < KT) { UP_ISSUE(jn); } else { cpcommit(); }
        cpwait2();
        __syncthreads();

        __half* As = (__half*)(dyn + (kt % DEPTH) * STAGE_B);
        __half* Bs = As + BM * LDSH;
#pragma unroll
        for (int ks = 0; ks < BKH / 16; ks++) {
            FragA af[2];
#pragma unroll
            for (int i = 0; i < 2; i++)
                wmma::load_matrix_sync(af[i], As + (wm + i * 16) * LDSH + ks * 16, LDSH);
#pragma unroll
            for (int j = 0; j < 2; j++) {
                FragB bb;
                wmma::load_matrix_sync(bb, Bs + (wn + j * 16) * LDSH + ks * 16, LDSH);
                wmma::mma_sync(accg[0][j], af[0], bb, accg[0][j]);
                wmma::mma_sync(accg[1][j], af[1], bb, accg[1][j]);
                wmma::load_matrix_sync(bb, Bs + (64 + wn + j * 16) * LDSH + ks * 16, LDSH);
                wmma::mma_sync(accu[0][j], af[0], bb, accu[0][j]);
                wmma::mma_sync(accu[1][j], af[1], bb, accu[1][j]);
            }
        }
        __syncthreads();
    }
#undef UP_ISSUE

    // epilogue: silu(Cg)*Cu -> g_A (fp16)   (Cg, Cu staged in smem, fp32)
    float* Cg = (float*)dyn;
    float* Cu = Cg + 128 * 64;
#pragma unroll
    for (int i = 0; i < 2; i++)
#pragma unroll
        for (int j = 0; j < 2; j++) {
            wmma::store_matrix_sync(Cg + (wm + i * 16) * 64 + wn + j * 16,
                                    accg[i][j], 64, wmma::mem_row_major);
            wmma::store_matrix_sync(Cu + (wm + i * 16) * 64 + wn + j * 16,
                                    accu[i][j], 64, wmma::mem_row_major);
        }
    __syncthreads();

#pragma unroll
    for (int it = 0; it < 8; it++) {
        int idx = tid + it * 256;
        int row = idx >> 4;
        int col = (idx & 15) * 4;
        if (row < rows) {
            float4 g = *(const float4*)(Cg + row * 64 + col);
            float4 u = *(const float4*)(Cu + row * 64 + col);
            __half2 h0 = __floats2half2_rn(silu_mul(g.x, u.x), silu_mul(g.y, u.y));
            __half2 h1 = __floats2half2_rn(silu_mul(g.z, u.z), silu_mul(g.w, u.w));
            __half2* dst = (__half2*)(g_A + (size_t)(base + m0 + row) * HALF_FFN
                                          + n0 + col);
            dst[0] = h0; dst[1] = h1;
        }
    }
}

// ---------------- DOWN GEMM: g_Y[slot] = coef * (g_A Wdown^T) ----------------
// grid (16 n-tiles of 128 over D_MODEL, MT_PAD m-tiles), complete bands.
__global__ void __launch_bounds__(256, 2)
down_gemm() {
    const int tiles_n = 16;
    int b    = blockIdx.y * tiles_n + blockIdx.x;
    int band = b / (MBAND * tiles_n);
    int rem  = b % (MBAND * tiles_n);
    int mt   = band * MBAND + (rem & (MBAND - 1));
    int nt   = rem >> 4;
    if (mt >= g_tile_offs[NE]) return;

    int e  = find_expert(mt);
    int m0 = (mt - g_tile_offs[e]) * BM;
    int rows = g_count[e] - m0; if (rows > BM) rows = BM;
    int base = g_offs[e];
    int n0   = nt * 128;
    int tid  = threadIdx.x, wid = tid >> 5;

    __shared__ int   s_tk[BM];
    __shared__ int   s_sl[BM];
    __shared__ float s_cf[BM];
    extern __shared__ __align__(16) char dyn[];
    uint32_t dbase = su32(dyn);

    if (tid < BM) {
        if (tid < rows) {
            s_tk[tid] = g_list_token[base + m0 + tid];
            s_sl[tid] = g_list_slot[base + m0 + tid];
            s_cf[tid] = g_list_coef[base + m0 + tid];
        } else { s_tk[tid] = 0; s_sl[tid] = 0; s_cf[tid] = 0.f; }
    }
    __syncthreads();

    const __half* we = g_wdh + (size_t)e * D_MODEL * HALF_FFN;
    int r0 = tid >> 3, q = tid & 7;
    const char* ap[4];
    const char* bp[4];
    uint32_t da[4], dbw[4];
#pragma unroll
    for (int p = 0; p < 4; p++) {
        int r = r0 + 32 * p;
        int ar = (r < rows) ? r : (rows - 1);
        ap[p] = (const char*)(g_A + (size_t)(base + m0 + ar) * HALF_FFN) + q * 16;
        bp[p] = (const char*)(we + (size_t)(n0 + r) * HALF_FFN) + q * 16;
        da[p]  = (uint32_t)(r * (LDSH * 2) + q * 16);
        dbw[p] = (uint32_t)(BM * (LDSH * 2) + r * (LDSH * 2) + q * 16);
    }

    int wm = (wid & 3) * 32;          // 4 m-strips of 32
    int wn = (wid >> 2) * 64;         // 2 n-strips of 64

    FragC acc[2][4];
#pragma unroll
    for (int i = 0; i < 2; i++)
#pragma unroll
        for (int j = 0; j < 4; j++) wmma::fill_fragment(acc[i][j], 0.f);

    const int KT = HALF_FFN / BKH;    // 64

#define DN_ISSUE(J) do {                                                     \
    uint32_t sb = dbase + ((J) % DEPTH) * STAGE_B;                           \
    size_t ko = (size_t)(J) * 128;                                           \
    _Pragma("unroll")                                                        \
    for (int p = 0; p < 4; p++) {                                            \
        cp16(sb + da[p],  ap[p] + ko);                                       \
        cp16(sb + dbw[p], bp[p] + ko);                                       \
    }                                                                        \
    cpcommit();                                                              \
} while (0)

    DN_ISSUE(0);
    DN_ISSUE(1);

#pragma unroll 1
    for (int kt = 0; kt < KT; kt++) {
        int jn = kt + DEPTH - 1;
        if (jn < KT) { DN_ISSUE(jn); } else { cpcommit(); }
        cpwait2();
        __syncthreads();

        __half* As = (__half*)(dyn + (kt % DEPTH) * STAGE_B);
        __half* Bs = As + BM * LDSH;
#pragma unroll
        for (int ks = 0; ks < BKH / 16; ks++) {
            FragA af[2];
#pragma unroll
            for (int i = 0; i < 2; i++)
                wmma::load_matrix_sync(af[i], As + (wm + i * 16) * LDSH + ks * 16, LDSH);
#pragma unroll
            for (int j = 0; j < 4; j++) {
                FragB bb;
                wmma::load_matrix_sync(bb, Bs + (wn + j * 16) * LDSH + ks * 16, LDSH);
                wmma::mma_sync(acc[0][j], af[0], bb, acc[0][j]);
                wmma::mma_sync(acc[1][j], af[1], bb, acc[1][j]);
            }
        }
        __syncthreads();
    }
#undef DN_ISSUE

    // epilogue: scale by coef, scatter to g_Y (C staged in smem, 64 KB)
    float* Cs = (float*)dyn;
#pragma unroll
    for (int i = 0; i < 2; i++)
#pragma unroll
        for (int j = 0; j < 4; j++)
            wmma::store_matrix_sync(Cs + (wm + i * 16) * 128 + wn + j * 16,
                                    acc[i][j], 128, wmma::mem_row_major);
    __syncthreads();

#pragma unroll
    for (int it = 0; it < 16; it++) {
        int idx = tid + it * 256;
        int row = idx >> 5;
        int col = (idx & 31) * 4;
        if (row < rows) {
            float c = s_cf[row];
            float4 v = *(const float4*)(Cs + row * 128 + col);
            v.x *= c; v.y *= c; v.z *= c; v.w *= c;
            *(float4*)(g_Y + ((size_t)s_sl[row] * T_TOKENS + s_tk[row]) * D_MODEL
                           + n0 + col) = v;
        }
    }
}

__global__ void combine_kernel(float* __restrict__ out) {
    size_t i = (size_t)blockIdx.x * blockDim.x + threadIdx.x;
    const size_t n4 = (size_t)T_TOKENS * D_MODEL / 4;
    if (i < n4) {
        const float4* y = (const float4*)g_Y;
        float4 a = y[i], b = y[i + n4];
        float4 r;
        r.x = a.x + b.x; r.y = a.y + b.y; r.z = a.z + b.z; r.w = a.w + b.w;
        ((float4*)out)[i] = r;
    }
}

// ---------------- host entry -------------------------------------------------
extern "C" void kernel_launch(void* const* d_in, const int* in_sizes, int n_in,
                              void* d_out, int out_size) {
    const float* x      = (const float*)d_in[0];
    const float* gate_w = (const float*)d_in[1];
    const float* w_up   = (const float*)d_in[2];
    const float* w_down = (const float*)d_in[3];
    float* out = (float*)d_out;

    cudaFuncSetAttribute(up_gemm,   cudaFuncAttributeMaxDynamicSharedMemorySize, DYN_SMEM);
    cudaFuncSetAttribute(down_gemm, cudaFuncAttributeMaxDynamicSharedMemorySize, DYN_SMEM);

    reset_kernel<<<1, 32>>>();
    // routing + fp16(x) + fp16(w_up), one launch (independent block roles)
    phase1_kernel<<<ROUTE_BLOCKS + CVTU_BLOCKS, 256>>>(x, gate_w,
                                                       (const float4*)w_up);
    offs_kernel<<<1, 1>>>();
    compact_kernel<<<NE, 1024>>>();

    // up GEMM + fp16(w_down) conversion riding in its shadow (extra y-rows)
    up_gemm<<<dim3(64, MT_PAD + CVD, 1), 256, DYN_SMEM>>>((const float4*)w_down);
    // down: 16 n-tiles (128 cols of D_MODEL) x MT_PAD m-tiles
    down_gemm<<<dim3(16, MT_PAD, 1), 256, DYN_SMEM>>>();

    combine_kernel<<<(T_TOKENS * D_MODEL / 4 + 255) / 256, 256>>>(out);
}

// round 14
// speedup vs baseline: 5.7333x; 1.0069x over previous
#include <cuda_runtime.h>
#include <cuda_fp16.h>
#include <mma.h>
#include <cstdint>

using namespace nvcuda;

#define D_MODEL   2048
#define FFN_DIM   8192
#define HALF_FFN  4096
#define NE        8
#define T_TOKENS  8192
#define MAXROWS   (T_TOKENS * 2)
#define NSEG      8                    // token segments for parallel compaction

#define BM 128
#define BKH 64                         // k elements per tile (fp16) = 128 B/row
#define LDSH 72                        // 64 + 8 pad halfs per smem row (144 B)
#define DEPTH 3
#define MBAND 16                       // m-tiles per swizzle band (~1 expert)
#define MT_PAD 144                     // GEMM m-tile rows (multiple of MBAND)
#define CVD 8                          // extra grid.y rows in up_gemm for w_down cvt
#define ROUTE_BLOCKS 1024              // routing blocks in phase1
#define CVTU_BLOCKS 1024               // w_up cvt blocks in phase1
#define STAGE_B (256 * LDSH * 2)       // A(128 rows) + B(128 rows) = 36864 B
#define DYN_SMEM (DEPTH * STAGE_B)     // 110592 B; 2 CTAs/SM

#define N4_WUP (NE * FFN_DIM * D_MODEL / 4)     // 33554432 float4
#define N4_WDN (NE * D_MODEL * HALF_FFN / 4)    // 16777216 float4

// ---------------- scratch (device globals; no runtime allocation) ----------
__device__ __half g_xh [(size_t)T_TOKENS * D_MODEL];        // 32 MB fp16 x
__device__ __half g_wuh[(size_t)NE * FFN_DIM * D_MODEL];    // 384 MB fp16 w_up
__device__ __half g_wdh[(size_t)NE * D_MODEL * HALF_FFN];   // 192 MB fp16 w_down
__device__ __half g_A  [(size_t)MAXROWS * HALF_FFN];        // 128 MB fp16 activated
__device__ float  g_Y  [(size_t)2 * T_TOKENS * D_MODEL];    // 128 MB per-slot outputs
__device__ int    g_topk_idx[T_TOKENS][2];
__device__ float  g_topk_w[T_TOKENS][2];
__device__ int    g_count[NE];
__device__ int    g_cnt_seg[NE][NSEG];
__device__ int    g_offs[NE + 1];
__device__ int    g_tile_offs[NE + 1];
__device__ int    g_list_token[MAXROWS];
__device__ int    g_list_slot[MAXROWS];
__device__ float  g_list_coef[MAXROWS];

// ---------------- PTX helpers ------------------------------------------------
__device__ __forceinline__ uint32_t su32(const void* p) {
    uint32_t r;
    asm("{ .reg .u64 t; cvta.to.shared.u64 t, %1; cvt.u32.u64 %0, t; }"
        : "=r"(r) : "l"(p));
    return r;
}
__device__ __forceinline__ void cp16(uint32_t d, const void* s) {
    asm volatile("cp.async.cg.shared.global [%0], [%1], 16;\n"
                 :: "r"(d), "l"(s) : "memory");
}
__device__ __forceinline__ void cpcommit() {
    asm volatile("cp.async.commit_group;\n" ::: "memory");
}
__device__ __forceinline__ void cpwait2() {
    asm volatile("cp.async.wait_group 2;\n" ::: "memory");
}

__device__ __forceinline__ void cvt4(const float4* __restrict__ s,
                                     uint2* __restrict__ d, int j) {
    float4 v = s[j];
    __half2 a = __floats2half2_rn(v.x, v.y);
    __half2 b = __floats2half2_rn(v.z, v.w);
    uint2 o;
    o.x = *(const uint32_t*)&a;
    o.y = *(const uint32_t*)&b;
    d[j] = o;
}

// ---------------- FP16 wmma types (fp32 accumulate) --------------------------
using FragA = wmma::fragment<wmma::matrix_a, 16, 16, 16, __half, wmma::row_major>;
using FragB = wmma::fragment<wmma::matrix_b, 16, 16, 16, __half, wmma::col_major>;
using FragC = wmma::fragment<wmma::accumulator, 16, 16, 16, float>;

__device__ __forceinline__ int find_expert(int ytile) {
    int e = 0;
#pragma unroll
    for (int i = 0; i < NE; i++) if (ytile >= g_tile_offs[i + 1]) e = i + 1;
    return e;
}

__device__ __forceinline__ float silu_mul(float g, float u) {
    return g * (1.f / (1.f + __expf(-g))) * u;
}

// ---------------- phase1: routing + fp16 cvt of x AND w_up (one launch) ------
__global__ void reset_kernel() {
    if (threadIdx.x < NE) g_count[threadIdx.x] = 0;
    if (threadIdx.x < NE * NSEG) ((int*)g_cnt_seg)[threadIdx.x] = 0;
}

__global__ void phase1_kernel(const float* __restrict__ x,
                              const float* __restrict__ gate_w,
                              const float4* __restrict__ wu_src) {
    if (blockIdx.x >= ROUTE_BLOCKS) {
        // ---- w_up fp32 -> fp16 (grid-stride over CVTU_BLOCKS blocks) ----
        int i = (blockIdx.x - ROUTE_BLOCKS) * blockDim.x + threadIdx.x;
        int stride = CVTU_BLOCKS * blockDim.x;
        uint2* d = (uint2*)g_wuh;
        for (; i < N4_WUP; i += stride) cvt4(wu_src, d, i);
        return;
    }

    // ---- routing: one warp per token; also emits fp16 copy of x ----
    int gwarp = (blockIdx.x * blockDim.x + threadIdx.x) >> 5;
    int lane  = threadIdx.x & 31;
    if (gwarp >= T_TOKENS) return;

    const float* xr = x + (size_t)gwarp * D_MODEL;
    __half* xh = g_xh + (size_t)gwarp * D_MODEL;
    float acc[NE];
#pragma unroll
    for (int e = 0; e < NE; e++) acc[e] = 0.f;
    for (int k = lane; k < D_MODEL; k += 32) {
        float xv = xr[k];
        xh[k] = __float2half_rn(xv);
#pragma unroll
        for (int e = 0; e < NE; e++) acc[e] += xv * gate_w[e * D_MODEL + k];
    }
#pragma unroll
    for (int off = 16; off > 0; off >>= 1)
#pragma unroll
        for (int e = 0; e < NE; e++)
            acc[e] += __shfl_xor_sync(0xffffffffu, acc[e], off);

    if (lane == 0) {
        int i0 = 0; float b0 = acc[0];
#pragma unroll
        for (int i = 1; i < NE; i++) if (acc[i] > b0) { b0 = acc[i]; i0 = i; }
        int i1 = -1; float b1 = -3.0e38f;
#pragma unroll
        for (int i = 0; i < NE; i++)
            if (i != i0 && acc[i] > b1) { b1 = acc[i]; i1 = i; }
        float e1  = expf(b1 - b0);
        float inv = 1.f / (1.f + e1);
        g_topk_idx[gwarp][0] = i0;  g_topk_idx[gwarp][1] = i1;
        g_topk_w[gwarp][0]   = inv; g_topk_w[gwarp][1]   = e1 * inv;
        int seg = gwarp >> 10;                  // 1024 tokens per segment
        atomicAdd(&g_count[i0], 1);
        atomicAdd(&g_count[i1], 1);
        atomicAdd(&g_cnt_seg[i0][seg], 1);
        atomicAdd(&g_cnt_seg[i1][seg], 1);
    }
}

// ---------------- parallel compaction: one block per (expert, segment) -------
// List order is identical to the old serial version (tokens ascending within
// each expert), so downstream results are bitwise unchanged. Block (0,0) also
// publishes g_offs / g_tile_offs (replacing the old offs_kernel launch).
__global__ void compact_kernel() {
    int e   = blockIdx.x >> 3;          // expert
    int seg = blockIdx.x & (NSEG - 1);  // token segment
    int tid = threadIdx.x;
    __shared__ int s[1024];

    if (e == 0 && seg == 0 && tid == 0) {
        int off = 0, toff = 0;
        for (int i = 0; i < NE; i++) {
            g_offs[i] = off; g_tile_offs[i] = toff;
            off  += g_count[i];
            toff += (g_count[i] + BM - 1) >> 7;
        }
        g_offs[NE] = off; g_tile_offs[NE] = toff;
    }

    // base = sum of counts of earlier experts + earlier segments of this expert
    int base = 0;
    for (int i = 0; i < e; i++) base += g_count[i];
    for (int i = 0; i < seg; i++) base += g_cnt_seg[e][i];

    int t = (seg << 10) + tid;
    int sel = 0, slot = 0; float w = 0.f;
    int i0 = g_topk_idx[t][0], i1 = g_topk_idx[t][1];
    if (i0 == e)      { sel = 1; slot = 0; w = g_topk_w[t][0]; }
    else if (i1 == e) { sel = 1; slot = 1; w = g_topk_w[t][1]; }

    s[tid] = sel; __syncthreads();
    for (int d = 1; d < 1024; d <<= 1) {
        int v = (tid >= d) ? s[tid - d] : 0;
        __syncthreads();
        s[tid] += v;
        __syncthreads();
    }
    if (sel) {
        int r = base + s[tid] - 1;
        g_list_token[r] = t;
        g_list_slot[r]  = slot;
        g_list_coef[r]  = w;
    }
}

// ---------------- UP GEMM (fused): g_A = silu(X Wg^T) * (X Wu^T) -------------
// grid (64 n-tiles, MT_PAD + CVD m-rows). Rows >= MT_PAD convert w_down to
// fp16 in the shadow of the tensor-bound GEMM waves.
// B stage: rows 0..63 = Wg rows, rows 64..127 = Wu rows. 2 CTAs per SM.
__global__ void __launch_bounds__(256, 2)
up_gemm(const float4* __restrict__ wd_src) {
    const int tiles_n = 64;

    if (blockIdx.y >= MT_PAD) {
        int i = (((int)blockIdx.y - MT_PAD) * tiles_n + (int)blockIdx.x)
                    * (int)blockDim.x + (int)threadIdx.x;
        int stride = CVD * tiles_n * (int)blockDim.x;
        uint2* d = (uint2*)g_wdh;
        for (; i < N4_WDN; i += stride) cvt4(wd_src, d, i);
        return;
    }

    int b    = blockIdx.y * tiles_n + blockIdx.x;
    int band = b / (MBAND * tiles_n);
    int rem  = b % (MBAND * tiles_n);
    int mt   = band * MBAND + (rem & (MBAND - 1));
    int nt   = rem >> 4;
    if (mt >= g_tile_offs[NE]) return;

    int e  = find_expert(mt);
    int m0 = (mt - g_tile_offs[e]) * BM;
    int rows = g_count[e] - m0; if (rows > BM) rows = BM;
    int base = g_offs[e];
    int n0   = nt * 64;
    int tid  = threadIdx.x, wid = tid >> 5;

    __shared__ int s_tok[BM];
    extern __shared__ __align__(16) char dyn[];
    uint32_t dbase = su32(dyn);

    if (tid < BM) {
        int rr = (tid < rows) ? tid : (rows - 1);
        s_tok[tid] = g_list_token[base + m0 + rr];
    }
    __syncthreads();

    const __half* we = g_wuh + (size_t)e * FFN_DIM * D_MODEL;
    int r0 = tid >> 3, q = tid & 7;
    const char* ap[4];
    const char* bp[4];
    uint32_t da[4], dbw[4];
#pragma unroll
    for (int p = 0; p < 4; p++) {
        int r = r0 + 32 * p;
        ap[p] = (const char*)(g_xh + (size_t)s_tok[r] * D_MODEL) + q * 16;
        int brow = (p < 2) ? (n0 + r) : (HALF_FFN + n0 + (r - 64));
        bp[p] = (const char*)(we + (size_t)brow * D_MODEL) + q * 16;
        da[p]  = (uint32_t)(r * (LDSH * 2) + q * 16);
        dbw[p] = (uint32_t)(BM * (LDSH * 2) + r * (LDSH * 2) + q * 16);
    }

    int wm = (wid & 3) * 32;          // 4 m-strips of 32
    int wn = (wid >> 2) * 32;         // 2 n-strips of 32

    FragC accg[2][2], accu[2][2];
#pragma unroll
    for (int i = 0; i < 2; i++)
#pragma unroll
        for (int j = 0; j < 2; j++) {
            wmma::fill_fragment(accg[i][j], 0.f);
            wmma::fill_fragment(accu[i][j], 0.f);
        }

    const int KT = D_MODEL / BKH;     // 32

#define UP_ISSUE(J) do {                                                     \
    uint32_t sb = dbase + ((J) % DEPTH) * STAGE_B;                           \
    size_t ko = (size_t)(J) * 128;                                           \
    _Pragma("unroll")                                                        \
    for (int p = 0; p < 4; p++) {                                            \
        cp16(sb + da[p],  ap[p] + ko);                                       \
        cp16(sb + dbw[p], bp[p] + ko);                                       \
    }                                                                        \
    cpcommit();                                                              \
} while (0)

    UP_ISSUE(0);
    UP_ISSUE(1);

#pragma unroll 1
    for (int kt = 0; kt < KT; kt++) {
        int jn = kt + DEPTH - 1;
        if (jn < KT) { UP_ISSUE(jn); } else { cpcommit(); }
        cpwait2();
        __syncthreads();

        __half* As = (__half*)(dyn + (kt % DEPTH) * STAGE_B);
        __half* Bs = As + BM * LDSH;
#pragma unroll
        for (int ks = 0; ks < BKH / 16; ks++) {
            FragA af[2];
#pragma unroll
            for (int i = 0; i < 2; i++)
                wmma::load_matrix_sync(af[i], As + (wm + i * 16) * LDSH + ks * 16, LDSH);
#pragma unroll
            for (int j = 0; j < 2; j++) {
                FragB bb;
                wmma::load_matrix_sync(bb, Bs + (wn + j * 16) * LDSH + ks * 16, LDSH);
                wmma::mma_sync(accg[0][j], af[0], bb, accg[0][j]);
                wmma::mma_sync(accg[1][j], af[1], bb, accg[1][j]);
                wmma::load_matrix_sync(bb, Bs + (64 + wn + j * 16) * LDSH + ks * 16, LDSH);
                wmma::mma_sync(accu[0][j], af[0], bb, accu[0][j]);
                wmma::mma_sync(accu[1][j], af[1], bb, accu[1][j]);
            }
        }
        __syncthreads();
    }
#undef UP_ISSUE

    // epilogue: silu(Cg)*Cu -> g_A (fp16)   (Cg, Cu staged in smem, fp32)
    float* Cg = (float*)dyn;
    float* Cu = Cg + 128 * 64;
#pragma unroll
    for (int i = 0; i < 2; i++)
#pragma unroll
        for (int j = 0; j < 2; j++) {
            wmma::store_matrix_sync(Cg + (wm + i * 16) * 64 + wn + j * 16,
                                    accg[i][j], 64, wmma::mem_row_major);
            wmma::store_matrix_sync(Cu + (wm + i * 16) * 64 + wn + j * 16,
                                    accu[i][j], 64, wmma::mem_row_major);
        }
    __syncthreads();

#pragma unroll
    for (int it = 0; it < 8; it++) {
        int idx = tid + it * 256;
        int row = idx >> 4;
        int col = (idx & 15) * 4;
        if (row < rows) {
            float4 g = *(const float4*)(Cg + row * 64 + col);
            float4 u = *(const float4*)(Cu + row * 64 + col);
            __half2 h0 = __floats2half2_rn(silu_mul(g.x, u.x), silu_mul(g.y, u.y));
            __half2 h1 = __floats2half2_rn(silu_mul(g.z, u.z), silu_mul(g.w, u.w));
            __half2* dst = (__half2*)(g_A + (size_t)(base + m0 + row) * HALF_FFN
                                          + n0 + col);
            dst[0] = h0; dst[1] = h1;
        }
    }
}

// ---------------- DOWN GEMM: g_Y[slot] = coef * (g_A Wdown^T) ----------------
// grid (16 n-tiles of 128 over D_MODEL, MT_PAD m-tiles), complete bands.
__global__ void __launch_bounds__(256, 2)
down_gemm() {
    const int tiles_n = 16;
    int b    = blockIdx.y * tiles_n + blockIdx.x;
    int band = b / (MBAND * tiles_n);
    int rem  = b % (MBAND * tiles_n);
    int mt   = band * MBAND + (rem & (MBAND - 1));
    int nt   = rem >> 4;
    if (mt >= g_tile_offs[NE]) return;

    int e  = find_expert(mt);
    int m0 = (mt - g_tile_offs[e]) * BM;
    int rows = g_count[e] - m0; if (rows > BM) rows = BM;
    int base = g_offs[e];
    int n0   = nt * 128;
    int tid  = threadIdx.x, wid = tid >> 5;

    __shared__ int   s_tk[BM];
    __shared__ int   s_sl[BM];
    __shared__ float s_cf[BM];
    extern __shared__ __align__(16) char dyn[];
    uint32_t dbase = su32(dyn);

    if (tid < BM) {
        if (tid < rows) {
            s_tk[tid] = g_list_token[base + m0 + tid];
            s_sl[tid] = g_list_slot[base + m0 + tid];
            s_cf[tid] = g_list_coef[base + m0 + tid];
        } else { s_tk[tid] = 0; s_sl[tid] = 0; s_cf[tid] = 0.f; }
    }
    __syncthreads();

    const __half* we = g_wdh + (size_t)e * D_MODEL * HALF_FFN;
    int r0 = tid >> 3, q = tid & 7;
    const char* ap[4];
    const char* bp[4];
    uint32_t da[4], dbw[4];
#pragma unroll
    for (int p = 0; p < 4; p++) {
        int r = r0 + 32 * p;
        int ar = (r < rows) ? r : (rows - 1);
        ap[p] = (const char*)(g_A + (size_t)(base + m0 + ar) * HALF_FFN) + q * 16;
        bp[p] = (const char*)(we + (size_t)(n0 + r) * HALF_FFN) + q * 16;
        da[p]  = (uint32_t)(r * (LDSH * 2) + q * 16);
        dbw[p] = (uint32_t)(BM * (LDSH * 2) + r * (LDSH * 2) + q * 16);
    }

    int wm = (wid & 3) * 32;          // 4 m-strips of 32
    int wn = (wid >> 2) * 64;         // 2 n-strips of 64

    FragC acc[2][4];
#pragma unroll
    for (int i = 0; i < 2; i++)
#pragma unroll
        for (int j = 0; j < 4; j++) wmma::fill_fragment(acc[i][j], 0.f);

    const int KT = HALF_FFN / BKH;    // 64

#define DN_ISSUE(J) do {                                                     \
    uint32_t sb = dbase + ((J) % DEPTH) * STAGE_B;                           \
    size_t ko = (size_t)(J) * 128;                                           \
    _Pragma("unroll")                                                        \
    for (int p = 0; p < 4; p++) {                                            \
        cp16(sb + da[p],  ap[p] + ko);                                       \
        cp16(sb + dbw[p], bp[p] + ko);                                       \
    }                                                                        \
    cpcommit();                                                              \
} while (0)

    DN_ISSUE(0);
    DN_ISSUE(1);

#pragma unroll 1
    for (int kt = 0; kt < KT; kt++) {
        int jn = kt + DEPTH - 1;
        if (jn < KT) { DN_ISSUE(jn); } else { cpcommit(); }
        cpwait2();
        __syncthreads();

        __half* As = (__half*)(dyn + (kt % DEPTH) * STAGE_B);
        __half* Bs = As + BM * LDSH;
#pragma unroll
        for (int ks = 0; ks < BKH / 16; ks++) {
            FragA af[2];
#pragma unroll
            for (int i = 0; i < 2; i++)
                wmma::load_matrix_sync(af[i], As + (wm + i * 16) * LDSH + ks * 16, LDSH);
#pragma unroll
            for (int j = 0; j < 4; j++) {
                FragB bb;
                wmma::load_matrix_sync(bb, Bs + (wn + j * 16) * LDSH + ks * 16, LDSH);
                wmma::mma_sync(acc[0][j], af[0], bb, acc[0][j]);
                wmma::mma_sync(acc[1][j], af[1], bb, acc[1][j]);
            }
        }
        __syncthreads();
    }
#undef DN_ISSUE

    // epilogue: scale by coef, scatter to g_Y (C staged in smem, 64 KB)
    float* Cs = (float*)dyn;
#pragma unroll
    for (int i = 0; i < 2; i++)
#pragma unroll
        for (int j = 0; j < 4; j++)
            wmma::store_matrix_sync(Cs + (wm + i * 16) * 128 + wn + j * 16,
                                    acc[i][j], 128, wmma::mem_row_major);
    __syncthreads();

#pragma unroll
    for (int it = 0; it < 16; it++) {
        int idx = tid + it * 256;
        int row = idx >> 5;
        int col = (idx & 31) * 4;
        if (row < rows) {
            float c = s_cf[row];
            float4 v = *(const float4*)(Cs + row * 128 + col);
            v.x *= c; v.y *= c; v.z *= c; v.w *= c;
            *(float4*)(g_Y + ((size_t)s_sl[row] * T_TOKENS + s_tk[row]) * D_MODEL
                           + n0 + col) = v;
        }
    }
}

__global__ void combine_kernel(float* __restrict__ out) {
    size_t i = (size_t)blockIdx.x * blockDim.x + threadIdx.x;
    const size_t n4 = (size_t)T_TOKENS * D_MODEL / 4;
    if (i < n4) {
        const float4* y = (const float4*)g_Y;
        float4 a = y[i], b = y[i + n4];
        float4 r;
        r.x = a.x + b.x; r.y = a.y + b.y; r.z = a.z + b.z; r.w = a.w + b.w;
        ((float4*)out)[i] = r;
    }
}

// ---------------- host entry -------------------------------------------------
extern "C" void kernel_launch(void* const* d_in, const int* in_sizes, int n_in,
                              void* d_out, int out_size) {
    const float* x      = (const float*)d_in[0];
    const float* gate_w = (const float*)d_in[1];
    const float* w_up   = (const float*)d_in[2];
    const float* w_down = (const float*)d_in[3];
    float* out = (float*)d_out;

    cudaFuncSetAttribute(up_gemm,   cudaFuncAttributeMaxDynamicSharedMemorySize, DYN_SMEM);
    cudaFuncSetAttribute(down_gemm, cudaFuncAttributeMaxDynamicSharedMemorySize, DYN_SMEM);

    reset_kernel<<<1, 128>>>();
    // routing + fp16(x) + fp16(w_up), one launch (independent block roles)
    phase1_kernel<<<ROUTE_BLOCKS + CVTU_BLOCKS, 256>>>(x, gate_w,
                                                       (const float4*)w_up);
    // parallel compaction (64 blocks) + offs/tile_offs computation
    compact_kernel<<<NE * NSEG, 1024>>>();

    // up GEMM + fp16(w_down) conversion riding in its shadow (extra y-rows)
    up_gemm<<<dim3(64, MT_PAD + CVD, 1), 256, DYN_SMEM>>>((const float4*)w_down);
    // down: 16 n-tiles (128 cols of D_MODEL) x MT_PAD m-tiles
    down_gemm<<<dim3(16, MT_PAD, 1), 256, DYN_SMEM>>>();

    combine_kernel<<<(T_TOKENS * D_MODEL / 4 + 255) / 256, 256>>>(out);
}

// round 15
// speedup vs baseline: 5.9491x; 1.0376x over previous
#include <cuda_runtime.h>
#include <cuda_fp16.h>
#include <mma.h>
#include <cstdint>

using namespace nvcuda;

#define D_MODEL   2048
#define FFN_DIM   8192
#define HALF_FFN  4096
#define NE        8
#define T_TOKENS  8192
#define MAXROWS   (T_TOKENS * 2)
#define NSEG      8                    // token segments for parallel compaction

#define BM 128
#define BKH 64                         // k elements per tile (fp16) = 128 B/row
#define LDSH 72                        // 64 + 8 pad halfs per smem row (144 B)
#define DEPTH 3
#define MBAND 16                       // m-tiles per swizzle band (~1 expert)
#define MT_PAD 144                     // GEMM m-tile rows (multiple of MBAND)
#define CVD 8                          // extra grid.y rows in up_gemm for w_down cvt
#define ROUTE_BLOCKS 1024              // routing blocks in phase1
#define CVTU_BLOCKS 1024               // w_up cvt blocks in phase1
#define STAGE_B (256 * LDSH * 2)       // A(128 rows) + B(128 rows) = 36864 B
#define DYN_SMEM (DEPTH * STAGE_B)     // 110592 B; 2 CTAs/SM

#define N4_WUP (NE * FFN_DIM * D_MODEL / 4)     // 33554432 float4
#define N4_WDN (NE * D_MODEL * HALF_FFN / 4)    // 16777216 float4

// ---------------- scratch (device globals; no runtime allocation) ----------
__device__ __half g_xh [(size_t)T_TOKENS * D_MODEL];        // 32 MB fp16 x
__device__ __half g_wuh[(size_t)NE * FFN_DIM * D_MODEL];    // 384 MB fp16 w_up
__device__ __half g_wdh[(size_t)NE * D_MODEL * HALF_FFN];   // 192 MB fp16 w_down
__device__ __half g_A  [(size_t)MAXROWS * HALF_FFN];        // 128 MB fp16 activated
__device__ float  g_Y  [(size_t)2 * T_TOKENS * D_MODEL];    // 128 MB per-slot outputs
__device__ int    g_topk_idx[T_TOKENS][2];
__device__ float  g_topk_w[T_TOKENS][2];
__device__ int    g_count[NE];
__device__ int    g_cnt_seg[NE][NSEG];
__device__ int    g_offs[NE + 1];
__device__ int    g_tile_offs[NE + 1];
__device__ int    g_list_token[MAXROWS];
__device__ int    g_list_slot[MAXROWS];
__device__ float  g_list_coef[MAXROWS];

// ---------------- PTX helpers ------------------------------------------------
__device__ __forceinline__ uint32_t su32(const void* p) {
    uint32_t r;
    asm("{ .reg .u64 t; cvta.to.shared.u64 t, %1; cvt.u32.u64 %0, t; }"
        : "=r"(r) : "l"(p));
    return r;
}
__device__ __forceinline__ void cp16(uint32_t d, const void* s) {
    asm volatile("cp.async.cg.shared.global [%0], [%1], 16;\n"
                 :: "r"(d), "l"(s) : "memory");
}
__device__ __forceinline__ void cpcommit() {
    asm volatile("cp.async.commit_group;\n" ::: "memory");
}
__device__ __forceinline__ void cpwait1() {
    asm volatile("cp.async.wait_group 1;\n" ::: "memory");
}

__device__ __forceinline__ void cvt4(const float4* __restrict__ s,
                                     uint2* __restrict__ d, int j) {
    float4 v = s[j];
    __half2 a = __floats2half2_rn(v.x, v.y);
    __half2 b = __floats2half2_rn(v.z, v.w);
    uint2 o;
    o.x = *(const uint32_t*)&a;
    o.y = *(const uint32_t*)&b;
    d[j] = o;
}

// ---------------- FP16 wmma types (fp32 accumulate) --------------------------
using FragA = wmma::fragment<wmma::matrix_a, 16, 16, 16, __half, wmma::row_major>;
using FragB = wmma::fragment<wmma::matrix_b, 16, 16, 16, __half, wmma::col_major>;
using FragC = wmma::fragment<wmma::accumulator, 16, 16, 16, float>;

__device__ __forceinline__ int find_expert(int ytile) {
    int e = 0;
#pragma unroll
    for (int i = 0; i < NE; i++) if (ytile >= g_tile_offs[i + 1]) e = i + 1;
    return e;
}

__device__ __forceinline__ float silu_mul(float g, float u) {
    return g * (1.f / (1.f + __expf(-g))) * u;
}

// ---------------- phase1: routing + fp16 cvt of x AND w_up (one launch) ------
__global__ void reset_kernel() {
    if (threadIdx.x < NE) g_count[threadIdx.x] = 0;
    if (threadIdx.x < NE * NSEG) ((int*)g_cnt_seg)[threadIdx.x] = 0;
}

__global__ void phase1_kernel(const float* __restrict__ x,
                              const float* __restrict__ gate_w,
                              const float4* __restrict__ wu_src) {
    if (blockIdx.x >= ROUTE_BLOCKS) {
        // ---- w_up fp32 -> fp16 (grid-stride over CVTU_BLOCKS blocks) ----
        int i = (blockIdx.x - ROUTE_BLOCKS) * blockDim.x + threadIdx.x;
        int stride = CVTU_BLOCKS * blockDim.x;
        uint2* d = (uint2*)g_wuh;
        for (; i < N4_WUP; i += stride) cvt4(wu_src, d, i);
        return;
    }

    // ---- routing: one warp per token; also emits fp16 copy of x ----
    int gwarp = (blockIdx.x * blockDim.x + threadIdx.x) >> 5;
    int lane  = threadIdx.x & 31;
    if (gwarp >= T_TOKENS) return;

    const float* xr = x + (size_t)gwarp * D_MODEL;
    __half* xh = g_xh + (size_t)gwarp * D_MODEL;
    float acc[NE];
#pragma unroll
    for (int e = 0; e < NE; e++) acc[e] = 0.f;
    for (int k = lane; k < D_MODEL; k += 32) {
        float xv = xr[k];
        xh[k] = __float2half_rn(xv);
#pragma unroll
        for (int e = 0; e < NE; e++) acc[e] += xv * gate_w[e * D_MODEL + k];
    }
#pragma unroll
    for (int off = 16; off > 0; off >>= 1)
#pragma unroll
        for (int e = 0; e < NE; e++)
            acc[e] += __shfl_xor_sync(0xffffffffu, acc[e], off);

    if (lane == 0) {
        int i0 = 0; float b0 = acc[0];
#pragma unroll
        for (int i = 1; i < NE; i++) if (acc[i] > b0) { b0 = acc[i]; i0 = i; }
        int i1 = -1; float b1 = -3.0e38f;
#pragma unroll
        for (int i = 0; i < NE; i++)
            if (i != i0 && acc[i] > b1) { b1 = acc[i]; i1 = i; }
        float e1  = expf(b1 - b0);
        float inv = 1.f / (1.f + e1);
        g_topk_idx[gwarp][0] = i0;  g_topk_idx[gwarp][1] = i1;
        g_topk_w[gwarp][0]   = inv; g_topk_w[gwarp][1]   = e1 * inv;
        int seg = gwarp >> 10;                  // 1024 tokens per segment
        atomicAdd(&g_count[i0], 1);
        atomicAdd(&g_count[i1], 1);
        atomicAdd(&g_cnt_seg[i0][seg], 1);
        atomicAdd(&g_cnt_seg[i1][seg], 1);
    }
}

// ---------------- parallel compaction: one block per (expert, segment) -------
__global__ void compact_kernel() {
    int e   = blockIdx.x >> 3;          // expert
    int seg = blockIdx.x & (NSEG - 1);  // token segment
    int tid = threadIdx.x;
    __shared__ int s[1024];

    if (e == 0 && seg == 0 && tid == 0) {
        int off = 0, toff = 0;
        for (int i = 0; i < NE; i++) {
            g_offs[i] = off; g_tile_offs[i] = toff;
            off  += g_count[i];
            toff += (g_count[i] + BM - 1) >> 7;
        }
        g_offs[NE] = off; g_tile_offs[NE] = toff;
    }

    int base = 0;
    for (int i = 0; i < e; i++) base += g_count[i];
    for (int i = 0; i < seg; i++) base += g_cnt_seg[e][i];

    int t = (seg << 10) + tid;
    int sel = 0, slot = 0; float w = 0.f;
    int i0 = g_topk_idx[t][0], i1 = g_topk_idx[t][1];
    if (i0 == e)      { sel = 1; slot = 0; w = g_topk_w[t][0]; }
    else if (i1 == e) { sel = 1; slot = 1; w = g_topk_w[t][1]; }

    s[tid] = sel; __syncthreads();
    for (int d = 1; d < 1024; d <<= 1) {
        int v = (tid >= d) ? s[tid - d] : 0;
        __syncthreads();
        s[tid] += v;
        __syncthreads();
    }
    if (sel) {
        int r = base + s[tid] - 1;
        g_list_token[r] = t;
        g_list_slot[r]  = slot;
        g_list_coef[r]  = w;
    }
}

// ---------------- UP GEMM (fused): g_A = silu(X Wg^T) * (X Wu^T) -------------
// Single barrier per k-tile: wait -> sync -> issue(kt+2) -> compute(kt).
// issue writes stage (kt-1)%3, which the sync just proved all warps are done
// reading. Overlap depth unchanged (2 stages in flight during compute).
__global__ void __launch_bounds__(256, 2)
up_gemm(const float4* __restrict__ wd_src) {
    const int tiles_n = 64;

    if (blockIdx.y >= MT_PAD) {
        int i = (((int)blockIdx.y - MT_PAD) * tiles_n + (int)blockIdx.x)
                    * (int)blockDim.x + (int)threadIdx.x;
        int stride = CVD * tiles_n * (int)blockDim.x;
        uint2* d = (uint2*)g_wdh;
        for (; i < N4_WDN; i += stride) cvt4(wd_src, d, i);
        return;
    }

    int b    = blockIdx.y * tiles_n + blockIdx.x;
    int band = b / (MBAND * tiles_n);
    int rem  = b % (MBAND * tiles_n);
    int mt   = band * MBAND + (rem & (MBAND - 1));
    int nt   = rem >> 4;
    if (mt >= g_tile_offs[NE]) return;

    int e  = find_expert(mt);
    int m0 = (mt - g_tile_offs[e]) * BM;
    int rows = g_count[e] - m0; if (rows > BM) rows = BM;
    int base = g_offs[e];
    int n0   = nt * 64;
    int tid  = threadIdx.x, wid = tid >> 5;

    __shared__ int s_tok[BM];
    extern __shared__ __align__(16) char dyn[];
    uint32_t dbase = su32(dyn);

    if (tid < BM) {
        int rr = (tid < rows) ? tid : (rows - 1);
        s_tok[tid] = g_list_token[base + m0 + rr];
    }
    __syncthreads();

    const __half* we = g_wuh + (size_t)e * FFN_DIM * D_MODEL;
    int r0 = tid >> 3, q = tid & 7;
    const char* ap[4];
    const char* bp[4];
    uint32_t da[4], dbw[4];
#pragma unroll
    for (int p = 0; p < 4; p++) {
        int r = r0 + 32 * p;
        ap[p] = (const char*)(g_xh + (size_t)s_tok[r] * D_MODEL) + q * 16;
        int brow = (p < 2) ? (n0 + r) : (HALF_FFN + n0 + (r - 64));
        bp[p] = (const char*)(we + (size_t)brow * D_MODEL) + q * 16;
        da[p]  = (uint32_t)(r * (LDSH * 2) + q * 16);
        dbw[p] = (uint32_t)(BM * (LDSH * 2) + r * (LDSH * 2) + q * 16);
    }

    int wm = (wid & 3) * 32;          // 4 m-strips of 32
    int wn = (wid >> 2) * 32;         // 2 n-strips of 32

    FragC accg[2][2], accu[2][2];
#pragma unroll
    for (int i = 0; i < 2; i++)
#pragma unroll
        for (int j = 0; j < 2; j++) {
            wmma::fill_fragment(accg[i][j], 0.f);
            wmma::fill_fragment(accu[i][j], 0.f);
        }

    const int KT = D_MODEL / BKH;     // 32

#define UP_ISSUE(J) do {                                                     \
    uint32_t sb = dbase + ((J) % DEPTH) * STAGE_B;                           \
    size_t ko = (size_t)(J) * 128;                                           \
    _Pragma("unroll")                                                        \
    for (int p = 0; p < 4; p++) {                                            \
        cp16(sb + da[p],  ap[p] + ko);                                       \
        cp16(sb + dbw[p], bp[p] + ko);                                       \
    }                                                                        \
    cpcommit();                                                              \
} while (0)

    UP_ISSUE(0);
    UP_ISSUE(1);

#pragma unroll 1
    for (int kt = 0; kt < KT; kt++) {
        cpwait1();                    // stage kt resident (<=1 newer pending)
        __syncthreads();              // all warps done reading stage kt-1
        int jn = kt + 2;
        if (jn < KT) { UP_ISSUE(jn); } else { cpcommit(); }

        __half* As = (__half*)(dyn + (kt % DEPTH) * STAGE_B);
        __half* Bs = As + BM * LDSH;
#pragma unroll
        for (int ks = 0; ks < BKH / 16; ks++) {
            FragA af[2];
#pragma unroll
            for (int i = 0; i < 2; i++)
                wmma::load_matrix_sync(af[i], As + (wm + i * 16) * LDSH + ks * 16, LDSH);
#pragma unroll
            for (int j = 0; j < 2; j++) {
                FragB bb;
                wmma::load_matrix_sync(bb, Bs + (wn + j * 16) * LDSH + ks * 16, LDSH);
                wmma::mma_sync(accg[0][j], af[0], bb, accg[0][j]);
                wmma::mma_sync(accg[1][j], af[1], bb, accg[1][j]);
                wmma::load_matrix_sync(bb, Bs + (64 + wn + j * 16) * LDSH + ks * 16, LDSH);
                wmma::mma_sync(accu[0][j], af[0], bb, accu[0][j]);
                wmma::mma_sync(accu[1][j], af[1], bb, accu[1][j]);
            }
        }
    }
#undef UP_ISSUE

    __syncthreads();                  // last k-tile fully consumed before reuse

    // epilogue: silu(Cg)*Cu -> g_A (fp16)   (Cg, Cu staged in smem, fp32)
    float* Cg = (float*)dyn;
    float* Cu = Cg + 128 * 64;
#pragma unroll
    for (int i = 0; i < 2; i++)
#pragma unroll
        for (int j = 0; j < 2; j++) {
            wmma::store_matrix_sync(Cg + (wm + i * 16) * 64 + wn + j * 16,
                                    accg[i][j], 64, wmma::mem_row_major);
            wmma::store_matrix_sync(Cu + (wm + i * 16) * 64 + wn + j * 16,
                                    accu[i][j], 64, wmma::mem_row_major);
        }
    __syncthreads();

#pragma unroll
    for (int it = 0; it < 8; it++) {
        int idx = tid + it * 256;
        int row = idx >> 4;
        int col = (idx & 15) * 4;
        if (row < rows) {
            float4 g = *(const float4*)(Cg + row * 64 + col);
            float4 u = *(const float4*)(Cu + row * 64 + col);
            __half2 h0 = __floats2half2_rn(silu_mul(g.x, u.x), silu_mul(g.y, u.y));
            __half2 h1 = __floats2half2_rn(silu_mul(g.z, u.z), silu_mul(g.w, u.w));
            __half2* dst = (__half2*)(g_A + (size_t)(base + m0 + row) * HALF_FFN
                                          + n0 + col);
            dst[0] = h0; dst[1] = h1;
        }
    }
}

// ---------------- DOWN GEMM: g_Y[slot] = coef * (g_A Wdown^T) ----------------
__global__ void __launch_bounds__(256, 2)
down_gemm() {
    const int tiles_n = 16;
    int b    = blockIdx.y * tiles_n + blockIdx.x;
    int band = b / (MBAND * tiles_n);
    int rem  = b % (MBAND * tiles_n);
    int mt   = band * MBAND + (rem & (MBAND - 1));
    int nt   = rem >> 4;
    if (mt >= g_tile_offs[NE]) return;

    int e  = find_expert(mt);
    int m0 = (mt - g_tile_offs[e]) * BM;
    int rows = g_count[e] - m0; if (rows > BM) rows = BM;
    int base = g_offs[e];
    int n0   = nt * 128;
    int tid  = threadIdx.x, wid = tid >> 5;

    __shared__ int   s_tk[BM];
    __shared__ int   s_sl[BM];
    __shared__ float s_cf[BM];
    extern __shared__ __align__(16) char dyn[];
    uint32_t dbase = su32(dyn);

    if (tid < BM) {
        if (tid < rows) {
            s_tk[tid] = g_list_token[base + m0 + tid];
            s_sl[tid] = g_list_slot[base + m0 + tid];
            s_cf[tid] = g_list_coef[base + m0 + tid];
        } else { s_tk[tid] = 0; s_sl[tid] = 0; s_cf[tid] = 0.f; }
    }
    __syncthreads();

    const __half* we = g_wdh + (size_t)e * D_MODEL * HALF_FFN;
    int r0 = tid >> 3, q = tid & 7;
    const char* ap[4];
    const char* bp[4];
    uint32_t da[4], dbw[4];
#pragma unroll
    for (int p = 0; p < 4; p++) {
        int r = r0 + 32 * p;
        int ar = (r < rows) ? r : (rows - 1);
        ap[p] = (const char*)(g_A + (size_t)(base + m0 + ar) * HALF_FFN) + q * 16;
        bp[p] = (const char*)(we + (size_t)(n0 + r) * HALF_FFN) + q * 16;
        da[p]  = (uint32_t)(r * (LDSH * 2) + q * 16);
        dbw[p] = (uint32_t)(BM * (LDSH * 2) + r * (LDSH * 2) + q * 16);
    }

    int wm = (wid & 3) * 32;          // 4 m-strips of 32
    int wn = (wid >> 2) * 64;         // 2 n-strips of 64

    FragC acc[2][4];
#pragma unroll
    for (int i = 0; i < 2; i++)
#pragma unroll
        for (int j = 0; j < 4; j++) wmma::fill_fragment(acc[i][j], 0.f);

    const int KT = HALF_FFN / BKH;    // 64

#define DN_ISSUE(J) do {                                                     \
    uint32_t sb = dbase + ((J) % DEPTH) * STAGE_B;                           \
    size_t ko = (size_t)(J) * 128;                                           \
    _Pragma("unroll")                                                        \
    for (int p = 0; p < 4; p++) {                                            \
        cp16(sb + da[p],  ap[p] + ko);                                       \
        cp16(sb + dbw[p], bp[p] + ko);                                       \
    }                                                                        \
    cpcommit();                                                              \
} while (0)

    DN_ISSUE(0);
    DN_ISSUE(1);

#pragma unroll 1
    for (int kt = 0; kt < KT; kt++) {
        cpwait1();
        __syncthreads();
        int jn = kt + 2;
        if (jn < KT) { DN_ISSUE(jn); } else { cpcommit(); }

        __half* As = (__half*)(dyn + (kt % DEPTH) * STAGE_B);
        __half* Bs = As + BM * LDSH;
#pragma unroll
        for (int ks = 0; ks < BKH / 16; ks++) {
            FragA af[2];
#pragma unroll
            for (int i = 0; i < 2; i++)
                wmma::load_matrix_sync(af[i], As + (wm + i * 16) * LDSH + ks * 16, LDSH);
#pragma unroll
            for (int j = 0; j < 4; j++) {
                FragB bb;
                wmma::load_matrix_sync(bb, Bs + (wn + j * 16) * LDSH + ks * 16, LDSH);
                wmma::mma_sync(acc[0][j], af[0], bb, acc[0][j]);
                wmma::mma_sync(acc[1][j], af[1], bb, acc[1][j]);
            }
        }
    }
#undef DN_ISSUE

    __syncthreads();                  // last k-tile fully consumed before reuse

    // epilogue: scale by coef, scatter to g_Y (C staged in smem, 64 KB)
    float* Cs = (float*)dyn;
#pragma unroll
    for (int i = 0; i < 2; i++)
#pragma unroll
        for (int j = 0; j < 4; j++)
            wmma::store_matrix_sync(Cs + (wm + i * 16) * 128 + wn + j * 16,
                                    acc[i][j], 128, wmma::mem_row_major);
    __syncthreads();

#pragma unroll
    for (int it = 0; it < 16; it++) {
        int idx = tid + it * 256;
        int row = idx >> 5;
        int col = (idx & 31) * 4;
        if (row < rows) {
            float c = s_cf[row];
            float4 v = *(const float4*)(Cs + row * 128 + col);
            v.x *= c; v.y *= c; v.z *= c; v.w *= c;
            *(float4*)(g_Y + ((size_t)s_sl[row] * T_TOKENS + s_tk[row]) * D_MODEL
                           + n0 + col) = v;
        }
    }
}

__global__ void combine_kernel(float* __restrict__ out) {
    size_t i = (size_t)blockIdx.x * blockDim.x + threadIdx.x;
    const size_t n4 = (size_t)T_TOKENS * D_MODEL / 4;
    if (i < n4) {
        const float4* y = (const float4*)g_Y;
        float4 a = y[i], b = y[i + n4];
        float4 r;
        r.x = a.x + b.x; r.y = a.y + b.y; r.z = a.z + b.z; r.w = a.w + b.w;
        ((float4*)out)[i] = r;
    }
}

// ---------------- host entry -------------------------------------------------
extern "C" void kernel_launch(void* const* d_in, const int* in_sizes, int n_in,
                              void* d_out, int out_size) {
    const float* x      = (const float*)d_in[0];
    const float* gate_w = (const float*)d_in[1];
    const float* w_up   = (const float*)d_in[2];
    const float* w_down = (const float*)d_in[3];
    float* out = (float*)d_out;

    cudaFuncSetAttribute(up_gemm,   cudaFuncAttributeMaxDynamicSharedMemorySize, DYN_SMEM);
    cudaFuncSetAttribute(down_gemm, cudaFuncAttributeMaxDynamicSharedMemorySize, DYN_SMEM);

    reset_kernel<<<1, 128>>>();
    phase1_kernel<<<ROUTE_BLOCKS + CVTU_BLOCKS, 256>>>(x, gate_w,
                                                       (const float4*)w_up);
    compact_kernel<<<NE * NSEG, 1024>>>();

    up_gemm<<<dim3(64, MT_PAD + CVD, 1), 256, DYN_SMEM>>>((const float4*)w_down);
    down_gemm<<<dim3(16, MT_PAD, 1), 256, DYN_SMEM>>>();

    combine_kernel<<<(T_TOKENS * D_MODEL / 4 + 255) / 256, 256>>>(out);
}

// round 17
// speedup vs baseline: 5.9499x; 1.0001x over previous
#include <cuda_runtime.h>
#include <cuda_fp16.h>
#include <mma.h>
#include <cstdint>

using namespace nvcuda;

#define D_MODEL   2048
#define FFN_DIM   8192
#define HALF_FFN  4096
#define NE        8
#define T_TOKENS  8192
#define MAXROWS   (T_TOKENS * 2)
#define NSEG      8                    // token segments for parallel compaction

#define BM 128
#define BKH 64                         // k elements per tile (fp16) = 128 B/row
#define LDSH 72                        // 64 + 8 pad halfs per smem row (144 B)
#define DEPTH 3
#define MBAND 16                       // m-tiles per swizzle band (~1 expert)
#define MT_PAD 144                     // GEMM m-tile rows (multiple of MBAND)
#define CVD 8                          // extra grid.y rows in up_gemm for w_down cvt
#define ROUTE_BLOCKS 1024              // routing blocks in phase1
#define CVTU_BLOCKS 1024               // w_up cvt blocks in phase1
#define STAGE_B (256 * LDSH * 2)       // A(128 rows) + B(128 rows) = 36864 B
#define DYN_SMEM (DEPTH * STAGE_B)     // 110592 B; 2 CTAs/SM

#define N4_WUP (NE * FFN_DIM * D_MODEL / 4)     // 33554432 float4
#define N4_WDN (NE * D_MODEL * HALF_FFN / 4)    // 16777216 float4

// ---------------- scratch (device globals; no runtime allocation) ----------
__device__ __half g_xh [(size_t)T_TOKENS * D_MODEL];        // 32 MB fp16 x
__device__ __half g_wuh[(size_t)NE * FFN_DIM * D_MODEL];    // 384 MB fp16 w_up
__device__ __half g_wdh[(size_t)NE * D_MODEL * HALF_FFN];   // 192 MB fp16 w_down
__device__ __half g_A  [(size_t)MAXROWS * HALF_FFN];        // 128 MB fp16 activated
__device__ float  g_Y  [(size_t)MAXROWS * D_MODEL];         // 128 MB down outputs (list rows)
__device__ int    g_topk_idx[T_TOKENS][2];
__device__ float  g_topk_w[T_TOKENS][2];
__device__ int    g_inv[T_TOKENS][2];                       // (token,slot) -> list row
__device__ int    g_count[NE];
__device__ int    g_cnt_seg[NE][NSEG];
__device__ int    g_offs[NE + 1];
__device__ int    g_tile_offs[NE + 1];
__device__ int    g_list_token[MAXROWS];

// ---------------- PTX helpers ------------------------------------------------
__device__ __forceinline__ uint32_t su32(const void* p) {
    uint32_t r;
    asm("{ .reg .u64 t; cvta.to.shared.u64 t, %1; cvt.u32.u64 %0, t; }"
        : "=r"(r) : "l"(p));
    return r;
}
__device__ __forceinline__ void cp16(uint32_t d, const void* s) {
    asm volatile("cp.async.cg.shared.global [%0], [%1], 16;\n"
                 :: "r"(d), "l"(s) : "memory");
}
__device__ __forceinline__ void cpcommit() {
    asm volatile("cp.async.commit_group;\n" ::: "memory");
}
__device__ __forceinline__ void cpwait1() {
    asm volatile("cp.async.wait_group 1;\n" ::: "memory");
}

__device__ __forceinline__ void cvt4(const float4* __restrict__ s,
                                     uint2* __restrict__ d, int j) {
    float4 v = s[j];
    __half2 a = __floats2half2_rn(v.x, v.y);
    __half2 b = __floats2half2_rn(v.z, v.w);
    uint2 o;
    o.x = *(const uint32_t*)&a;
    o.y = *(const uint32_t*)&b;
    d[j] = o;
}

// ---------------- FP16 wmma types (fp32 accumulate) --------------------------
using FragA = wmma::fragment<wmma::matrix_a, 16, 16, 16, __half, wmma::row_major>;
using FragB = wmma::fragment<wmma::matrix_b, 16, 16, 16, __half, wmma::col_major>;
using FragC = wmma::fragment<wmma::accumulator, 16, 16, 16, float>;

__device__ __forceinline__ int find_expert(int ytile) {
    int e = 0;
#pragma unroll
    for (int i = 0; i < NE; i++) if (ytile >= g_tile_offs[i + 1]) e = i + 1;
    return e;
}

__device__ __forceinline__ float silu_mul(float g, float u) {
    return g * (1.f / (1.f + __expf(-g))) * u;
}

// ---------------- phase1: routing + fp16 cvt of x AND w_up (one launch) ------
__global__ void reset_kernel() {
    if (threadIdx.x < NE) g_count[threadIdx.x] = 0;
    if (threadIdx.x < NE * NSEG) ((int*)g_cnt_seg)[threadIdx.x] = 0;
}

__global__ void phase1_kernel(const float* __restrict__ x,
                              const float* __restrict__ gate_w,
                              const float4* __restrict__ wu_src) {
    if (blockIdx.x >= ROUTE_BLOCKS) {
        // ---- w_up fp32 -> fp16 (grid-stride over CVTU_BLOCKS blocks) ----
        int i = (blockIdx.x - ROUTE_BLOCKS) * blockDim.x + threadIdx.x;
        int stride = CVTU_BLOCKS * blockDim.x;
        uint2* d = (uint2*)g_wuh;
        for (; i < N4_WUP; i += stride) cvt4(wu_src, d, i);
        return;
    }

    // ---- routing: one warp per token; also emits fp16 copy of x ----
    int gwarp = (blockIdx.x * blockDim.x + threadIdx.x) >> 5;
    int lane  = threadIdx.x & 31;
    if (gwarp >= T_TOKENS) return;

    const float* xr = x + (size_t)gwarp * D_MODEL;
    __half* xh = g_xh + (size_t)gwarp * D_MODEL;
    float acc[NE];
#pragma unroll
    for (int e = 0; e < NE; e++) acc[e] = 0.f;
    for (int k = lane; k < D_MODEL; k += 32) {
        float xv = xr[k];
        xh[k] = __float2half_rn(xv);
#pragma unroll
        for (int e = 0; e < NE; e++) acc[e] += xv * gate_w[e * D_MODEL + k];
    }
#pragma unroll
    for (int off = 16; off > 0; off >>= 1)
#pragma unroll
        for (int e = 0; e < NE; e++)
            acc[e] += __shfl_xor_sync(0xffffffffu, acc[e], off);

    if (lane == 0) {
        int i0 = 0; float b0 = acc[0];
#pragma unroll
        for (int i = 1; i < NE; i++) if (acc[i] > b0) { b0 = acc[i]; i0 = i; }
        int i1 = -1; float b1 = -3.0e38f;
#pragma unroll
        for (int i = 0; i < NE; i++)
            if (i != i0 && acc[i] > b1) { b1 = acc[i]; i1 = i; }
        float e1  = expf(b1 - b0);
        float inv = 1.f / (1.f + e1);
        g_topk_idx[gwarp][0] = i0;  g_topk_idx[gwarp][1] = i1;
        g_topk_w[gwarp][0]   = inv; g_topk_w[gwarp][1]   = e1 * inv;
        int seg = gwarp >> 10;                  // 1024 tokens per segment
        atomicAdd(&g_count[i0], 1);
        atomicAdd(&g_count[i1], 1);
        atomicAdd(&g_cnt_seg[i0][seg], 1);
        atomicAdd(&g_cnt_seg[i1][seg], 1);
    }
}

// ---------------- parallel compaction: one block per (expert, segment) -------
// Also writes the inverse map (token,slot) -> list row for combine.
__global__ void compact_kernel() {
    int e   = blockIdx.x >> 3;          // expert
    int seg = blockIdx.x & (NSEG - 1);  // token segment
    int tid = threadIdx.x;
    __shared__ int s[1024];

    if (e == 0 && seg == 0 && tid == 0) {
        int off = 0, toff = 0;
        for (int i = 0; i < NE; i++) {
            g_offs[i] = off; g_tile_offs[i] = toff;
            off  += g_count[i];
            toff += (g_count[i] + BM - 1) >> 7;
        }
        g_offs[NE] = off; g_tile_offs[NE] = toff;
    }

    int base = 0;
    for (int i = 0; i < e; i++) base += g_count[i];
    for (int i = 0; i < seg; i++) base += g_cnt_seg[e][i];

    int t = (seg << 10) + tid;
    int sel = 0, slot = 0;
    int i0 = g_topk_idx[t][0], i1 = g_topk_idx[t][1];
    if (i0 == e)      { sel = 1; slot = 0; }
    else if (i1 == e) { sel = 1; slot = 1; }

    s[tid] = sel; __syncthreads();
    for (int d = 1; d < 1024; d <<= 1) {
        int v = (tid >= d) ? s[tid - d] : 0;
        __syncthreads();
        s[tid] += v;
        __syncthreads();
    }
    if (sel) {
        int r = base + s[tid] - 1;
        g_list_token[r] = t;
        g_inv[t][slot]  = r;
    }
}

// ---------------- UP GEMM (fused): g_A = silu(X Wg^T) * (X Wu^T) -------------
// Single barrier per k-tile (R15 proven order): wait -> sync -> issue -> compute.
__global__ void __launch_bounds__(256, 2)
up_gemm(const float4* __restrict__ wd_src) {
    const int tiles_n = 64;

    if (blockIdx.y >= MT_PAD) {
        int i = (((int)blockIdx.y - MT_PAD) * tiles_n + (int)blockIdx.x)
                    * (int)blockDim.x + (int)threadIdx.x;
        int stride = CVD * tiles_n * (int)blockDim.x;
        uint2* d = (uint2*)g_wdh;
        for (; i < N4_WDN; i += stride) cvt4(wd_src, d, i);
        return;
    }

    int b    = blockIdx.y * tiles_n + blockIdx.x;
    int band = b / (MBAND * tiles_n);
    int rem  = b % (MBAND * tiles_n);
    int mt   = band * MBAND + (rem & (MBAND - 1));
    int nt   = rem >> 4;
    if (mt >= g_tile_offs[NE]) return;

    int e  = find_expert(mt);
    int m0 = (mt - g_tile_offs[e]) * BM;
    int rows = g_count[e] - m0; if (rows > BM) rows = BM;
    int base = g_offs[e];
    int n0   = nt * 64;
    int tid  = threadIdx.x, wid = tid >> 5;

    __shared__ int s_tok[BM];
    extern __shared__ __align__(16) char dyn[];
    uint32_t dbase = su32(dyn);

    if (tid < BM) {
        int rr = (tid < rows) ? tid : (rows - 1);
        s_tok[tid] = g_list_token[base + m0 + rr];
    }
    __syncthreads();

    const __half* we = g_wuh + (size_t)e * FFN_DIM * D_MODEL;
    int r0 = tid >> 3, q = tid & 7;
    const char* ap[4];
    const char* bp[4];
    uint32_t da[4], dbw[4];
#pragma unroll
    for (int p = 0; p < 4; p++) {
        int r = r0 + 32 * p;
        ap[p] = (const char*)(g_xh + (size_t)s_tok[r] * D_MODEL) + q * 16;
        int brow = (p < 2) ? (n0 + r) : (HALF_FFN + n0 + (r - 64));
        bp[p] = (const char*)(we + (size_t)brow * D_MODEL) + q * 16;
        da[p]  = (uint32_t)(r * (LDSH * 2) + q * 16);
        dbw[p] = (uint32_t)(BM * (LDSH * 2) + r * (LDSH * 2) + q * 16);
    }

    int wm = (wid & 3) * 32;          // 4 m-strips of 32
    int wn = (wid >> 2) * 32;         // 2 n-strips of 32

    FragC accg[2][2], accu[2][2];
#pragma unroll
    for (int i = 0; i < 2; i++)
#pragma unroll
        for (int j = 0; j < 2; j++) {
            wmma::fill_fragment(accg[i][j], 0.f);
            wmma::fill_fragment(accu[i][j], 0.f);
        }

    const int KT = D_MODEL / BKH;     // 32

#define UP_ISSUE(J) do {                                                     \
    uint32_t sb = dbase + ((J) % DEPTH) * STAGE_B;                           \
    size_t ko = (size_t)(J) * 128;                                           \
    _Pragma("unroll")                                                        \
    for (int p = 0; p < 4; p++) {                                            \
        cp16(sb + da[p],  ap[p] + ko);                                       \
        cp16(sb + dbw[p], bp[p] + ko);                                       \
    }                                                                        \
    cpcommit();                                                              \
} while (0)

    UP_ISSUE(0);
    UP_ISSUE(1);

#pragma unroll 1
    for (int kt = 0; kt < KT; kt++) {
        cpwait1();                    // stage kt resident (<=1 newer pending)
        __syncthreads();              // all warps' copies published; kt-1 consumed
        int jn = kt + 2;
        if (jn < KT) { UP_ISSUE(jn); } else { cpcommit(); }

        __half* As = (__half*)(dyn + (kt % DEPTH) * STAGE_B);
        __half* Bs = As + BM * LDSH;
#pragma unroll
        for (int ks = 0; ks < BKH / 16; ks++) {
            FragA af[2];
#pragma unroll
            for (int i = 0; i < 2; i++)
                wmma::load_matrix_sync(af[i], As + (wm + i * 16) * LDSH + ks * 16, LDSH);
#pragma unroll
            for (int j = 0; j < 2; j++) {
                FragB bb;
                wmma::load_matrix_sync(bb, Bs + (wn + j * 16) * LDSH + ks * 16, LDSH);
                wmma::mma_sync(accg[0][j], af[0], bb, accg[0][j]);
                wmma::mma_sync(accg[1][j], af[1], bb, accg[1][j]);
                wmma::load_matrix_sync(bb, Bs + (64 + wn + j * 16) * LDSH + ks * 16, LDSH);
                wmma::mma_sync(accu[0][j], af[0], bb, accu[0][j]);
                wmma::mma_sync(accu[1][j], af[1], bb, accu[1][j]);
            }
        }
    }
#undef UP_ISSUE

    __syncthreads();                  // last k-tile fully consumed before reuse

    // epilogue: silu(Cg)*Cu -> g_A (fp16)   (Cg, Cu staged in smem, fp32)
    float* Cg = (float*)dyn;
    float* Cu = Cg + 128 * 64;
#pragma unroll
    for (int i = 0; i < 2; i++)
#pragma unroll
        for (int j = 0; j < 2; j++) {
            wmma::store_matrix_sync(Cg + (wm + i * 16) * 64 + wn + j * 16,
                                    accg[i][j], 64, wmma::mem_row_major);
            wmma::store_matrix_sync(Cu + (wm + i * 16) * 64 + wn + j * 16,
                                    accu[i][j], 64, wmma::mem_row_major);
        }
    __syncthreads();

#pragma unroll
    for (int it = 0; it < 8; it++) {
        int idx = tid + it * 256;
        int row = idx >> 4;
        int col = (idx & 15) * 4;
        if (row < rows) {
            float4 g = *(const float4*)(Cg + row * 64 + col);
            float4 u = *(const float4*)(Cu + row * 64 + col);
            __half2 h0 = __floats2half2_rn(silu_mul(g.x, u.x), silu_mul(g.y, u.y));
            __half2 h1 = __floats2half2_rn(silu_mul(g.z, u.z), silu_mul(g.w, u.w));
            __half2* dst = (__half2*)(g_A + (size_t)(base + m0 + row) * HALF_FFN
                                          + n0 + col);
            dst[0] = h0; dst[1] = h1;
        }
    }
}

// ---------------- DOWN GEMM: g_Y[list] = g_A Wdown^T (coef applied later) ----
__global__ void __launch_bounds__(256, 2)
down_gemm() {
    const int tiles_n = 16;
    int b    = blockIdx.y * tiles_n + blockIdx.x;
    int band = b / (MBAND * tiles_n);
    int rem  = b % (MBAND * tiles_n);
    int mt   = band * MBAND + (rem & (MBAND - 1));
    int nt   = rem >> 4;
    if (mt >= g_tile_offs[NE]) return;

    int e  = find_expert(mt);
    int m0 = (mt - g_tile_offs[e]) * BM;
    int rows = g_count[e] - m0; if (rows > BM) rows = BM;
    int base = g_offs[e];
    int n0   = nt * 128;
    int tid  = threadIdx.x, wid = tid >> 5;

    extern __shared__ __align__(16) char dyn[];
    uint32_t dbase = su32(dyn);

    const __half* we = g_wdh + (size_t)e * D_MODEL * HALF_FFN;
    int r0 = tid >> 3, q = tid & 7;
    const char* ap[4];
    const char* bp[4];
    uint32_t da[4], dbw[4];
#pragma unroll
    for (int p = 0; p < 4; p++) {
        int r = r0 + 32 * p;
        int ar = (r < rows) ? r : (rows - 1);
        ap[p] = (const char*)(g_A + (size_t)(base + m0 + ar) * HALF_FFN) + q * 16;
        bp[p] = (const char*)(we + (size_t)(n0 + r) * HALF_FFN) + q * 16;
        da[p]  = (uint32_t)(r * (LDSH * 2) + q * 16);
        dbw[p] = (uint32_t)(BM * (LDSH * 2) + r * (LDSH * 2) + q * 16);
    }

    int wm = (wid & 3) * 32;          // 4 m-strips of 32
    int wn = (wid >> 2) * 64;         // 2 n-strips of 64

    FragC acc[2][4];
#pragma unroll
    for (int i = 0; i < 2; i++)
#pragma unroll
        for (int j = 0; j < 4; j++) wmma::fill_fragment(acc[i][j], 0.f);

    const int KT = HALF_FFN / BKH;    // 64

#define DN_ISSUE(J) do {                                                     \
    uint32_t sb = dbase + ((J) % DEPTH) * STAGE_B;                           \
    size_t ko = (size_t)(J) * 128;                                           \
    _Pragma("unroll")                                                        \
    for (int p = 0; p < 4; p++) {                                            \
        cp16(sb + da[p],  ap[p] + ko);                                       \
        cp16(sb + dbw[p], bp[p] + ko);                                       \
    }                                                                        \
    cpcommit();                                                              \
} while (0)

    DN_ISSUE(0);
    DN_ISSUE(1);

#pragma unroll 1
    for (int kt = 0; kt < KT; kt++) {
        cpwait1();
        __syncthreads();
        int jn = kt + 2;
        if (jn < KT) { DN_ISSUE(jn); } else { cpcommit(); }

        __half* As = (__half*)(dyn + (kt % DEPTH) * STAGE_B);
        __half* Bs = As + BM * LDSH;
#pragma unroll
        for (int ks = 0; ks < BKH / 16; ks++) {
            FragA af[2];
#pragma unroll
            for (int i = 0; i < 2; i++)
                wmma::load_matrix_sync(af[i], As + (wm + i * 16) * LDSH + ks * 16, LDSH);
#pragma unroll
            for (int j = 0; j < 4; j++) {
                FragB bb;
                wmma::load_matrix_sync(bb, Bs + (wn + j * 16) * LDSH + ks * 16, LDSH);
                wmma::mma_sync(acc[0][j], af[0], bb, acc[0][j]);
                wmma::mma_sync(acc[1][j], af[1], bb, acc[1][j]);
            }
        }
    }
#undef DN_ISSUE

    // epilogue: raw GEMM result to contiguous list rows of g_Y (coef later).
    if (rows == BM) {
#pragma unroll
        for (int i = 0; i < 2; i++)
#pragma unroll
            for (int j = 0; j < 4; j++)
                wmma::store_matrix_sync(
                    g_Y + (size_t)(base + m0 + wm + i * 16) * D_MODEL + n0 + wn + j * 16,
                    acc[i][j], D_MODEL, wmma::mem_row_major);
    } else {
        __syncthreads();              // last k-tile consumed before smem reuse
        float* Cs = (float*)dyn;
#pragma unroll
        for (int i = 0; i < 2; i++)
#pragma unroll
            for (int j = 0; j < 4; j++)
                wmma::store_matrix_sync(Cs + (wm + i * 16) * 128 + wn + j * 16,
                                        acc[i][j], 128, wmma::mem_row_major);
        __syncthreads();
#pragma unroll
        for (int it = 0; it < 16; it++) {
            int idx = tid + it * 256;
            int row = idx >> 5;
            int col = (idx & 31) * 4;
            if (row < rows) {
                *(float4*)(g_Y + (size_t)(base + m0 + row) * D_MODEL + n0 + col) =
                    *(const float4*)(Cs + row * 128 + col);
            }
        }
    }
}

// ---------------- combine: out[t] = w0*Y[inv0] + w1*Y[inv1] ------------------
__global__ void combine_kernel(float* __restrict__ out) {
    int idx = blockIdx.x * blockDim.x + threadIdx.x;
    if (idx >= T_TOKENS * (D_MODEL / 4)) return;
    int t = idx >> 9;                  // D_MODEL/4 = 512
    int c = (idx & 511) << 2;
    float w0 = g_topk_w[t][0], w1 = g_topk_w[t][1];
    int   r0 = g_inv[t][0],    r1 = g_inv[t][1];
    float4 a = *(const float4*)(g_Y + (size_t)r0 * D_MODEL + c);
    float4 b = *(const float4*)(g_Y + (size_t)r1 * D_MODEL + c);
    float4 r;
    r.x = w0 * a.x + w1 * b.x;
    r.y = w0 * a.y + w1 * b.y;
    r.z = w0 * a.z + w1 * b.z;
    r.w = w0 * a.w + w1 * b.w;
    *(float4*)(out + (size_t)t * D_MODEL + c) = r;
}

// ---------------- host entry -------------------------------------------------
extern "C" void kernel_launch(void* const* d_in, const int* in_sizes, int n_in,
                              void* d_out, int out_size) {
    const float* x      = (const float*)d_in[0];
    const float* gate_w = (const float*)d_in[1];
    const float* w_up   = (const float*)d_in[2];
    const float* w_down = (const float*)d_in[3];
    float* out = (float*)d_out;

    cudaFuncSetAttribute(up_gemm,   cudaFuncAttributeMaxDynamicSharedMemorySize, DYN_SMEM);
    cudaFuncSetAttribute(down_gemm, cudaFuncAttributeMaxDynamicSharedMemorySize, DYN_SMEM);

    reset_kernel<<<1, 128>>>();
    phase1_kernel<<<ROUTE_BLOCKS + CVTU_BLOCKS, 256>>>(x, gate_w,
                                                       (const float4*)w_up);
    compact_kernel<<<NE * NSEG, 1024>>>();

    up_gemm<<<dim3(64, MT_PAD + CVD, 1), 256, DYN_SMEM>>>((const float4*)w_down);
    down_gemm<<<dim3(16, MT_PAD, 1), 256, DYN_SMEM>>>();

    combine_kernel<<<(T_TOKENS * (D_MODEL / 4) + 255) / 256, 256>>>(out);
}